// round 4
// baseline (speedup 1.0000x reference)
#include <cuda_runtime.h>
#include <cuda_bf16.h>
#include <mma.h>

using namespace nvcuda;

// Problem constants
#define BATCH 4
#define SEQ 2048
#define DMODEL 1024
#define NHEADS 16
#define DK 64
#define MTOT (BATCH * SEQ)   // 8192

// ---------------- scratch (static device globals; no runtime allocation) ----
__device__ float g_Q[BATCH * NHEADS * SEQ * DK];     // [B,H,S,DK]
__device__ float g_K[BATCH * NHEADS * SEQ * DK];
__device__ float g_V[BATCH * NHEADS * SEQ * DK];
__device__ float g_ctx[MTOT * DMODEL];               // [B*S, D]
__device__ float g_proj[MTOT * DMODEL];              // ctx @ Wo + bo
__device__ float g_bias_rep[4 * 16 * DMODEL];        // 4 biases replicated to 16 rows

// ---------------- bias replication (so biases can be loaded as accum frags) --
__global__ void fill_bias_rep(const float* __restrict__ bq, const float* __restrict__ bk,
                              const float* __restrict__ bv, const float* __restrict__ bo) {
    int idx = blockIdx.x * blockDim.x + threadIdx.x;   // 4*16*1024 = 65536
    if (idx >= 4 * 16 * DMODEL) return;
    int which = idx >> 14;          // /(16*1024)
    int n = idx & (DMODEL - 1);
    const float* src = (which == 0) ? bq : (which == 1) ? bk : (which == 2) ? bv : bo;
    g_bias_rep[idx] = src[n];
}

// ---------------- TF32 WMMA GEMM: C[M,N] = A[M,K] @ W[K,N] + bias ------------
// BM=128, BN=128, BK=32; 8 warps as 4(M) x 2(N); warp tile 32x64 = 2x4 frags.
// out_sel: 0/1/2 -> scatter into g_Q/g_K/g_V as [B,H,S,DK]; 3 -> plain g_proj.
#define GBM 128
#define GBN 128
#define GBK 32
#define GLDA 36    // 144B rows (mult of 16B)
#define GLDB 132   // 528B rows

__global__ void __launch_bounds__(256, 2)
gemm_tf32(const float* __restrict__ Aext, const float* __restrict__ W,
          int bias_idx, int out_sel, int use_ctx) {
    const float* A = use_ctx ? g_ctx : Aext;
    float* out = (out_sel == 0) ? g_Q : (out_sel == 1) ? g_K : (out_sel == 2) ? g_V : g_proj;
    const float* brep = g_bias_rep + bias_idx * 16 * DMODEL;

    __shared__ __align__(128) float As[GBM * GLDA];
    __shared__ __align__(128) float Bs[GBK * GLDB];

    const int t = threadIdx.x;
    const int warp = t >> 5;
    const int wm = warp >> 1;   // 0..3 (M)
    const int wn = warp & 1;    // 0..1 (N)
    const int row0 = blockIdx.y * GBM;
    const int col0 = blockIdx.x * GBN;

    wmma::fragment<wmma::accumulator, 16, 16, 8, float> c[2][4];
#pragma unroll
    for (int i = 0; i < 2; i++)
#pragma unroll
        for (int j = 0; j < 4; j++)
            wmma::load_matrix_sync(c[i][j], brep + col0 + wn * 64 + j * 16, DMODEL,
                                   wmma::mem_row_major);

    for (int kt = 0; kt < DMODEL; kt += GBK) {
        // stage A tile: 128 x 32 (1024 float4, 4 per thread)
#pragma unroll
        for (int i = 0; i < 4; i++) {
            int idx = t + i * 256;
            int r = idx >> 3, v = idx & 7;
            float4 val = *(const float4*)(A + (size_t)(row0 + r) * DMODEL + kt + v * 4);
            *(float4*)(As + r * GLDA + v * 4) = val;
        }
        // stage B tile: 32 x 128
#pragma unroll
        for (int i = 0; i < 4; i++) {
            int idx = t + i * 256;
            int r = idx >> 5, v = idx & 31;
            float4 val = *(const float4*)(W + (size_t)(kt + r) * DMODEL + col0 + v * 4);
            *(float4*)(Bs + r * GLDB + v * 4) = val;
        }
        __syncthreads();

#pragma unroll
        for (int ks = 0; ks < GBK / 8; ks++) {
            wmma::fragment<wmma::matrix_a, 16, 16, 8, wmma::precision::tf32, wmma::row_major> a[2];
            wmma::fragment<wmma::matrix_b, 16, 16, 8, wmma::precision::tf32, wmma::row_major> b[4];
#pragma unroll
            for (int i = 0; i < 2; i++) {
                wmma::load_matrix_sync(a[i], As + (wm * 32 + i * 16) * GLDA + ks * 8, GLDA);
#pragma unroll
                for (int e = 0; e < a[i].num_elements; e++)
                    a[i].x[e] = wmma::__float_to_tf32(a[i].x[e]);
            }
#pragma unroll
            for (int j = 0; j < 4; j++) {
                wmma::load_matrix_sync(b[j], Bs + ks * 8 * GLDB + wn * 64 + j * 16, GLDB);
#pragma unroll
                for (int e = 0; e < b[j].num_elements; e++)
                    b[j].x[e] = wmma::__float_to_tf32(b[j].x[e]);
            }
#pragma unroll
            for (int i = 0; i < 2; i++)
#pragma unroll
                for (int j = 0; j < 4; j++)
                    wmma::mma_sync(c[i][j], a[i], b[j], c[i][j]);
        }
        __syncthreads();
    }

    // epilogue
#pragma unroll
    for (int i = 0; i < 2; i++) {
        int r0 = row0 + wm * 32 + i * 16;
#pragma unroll
        for (int j = 0; j < 4; j++) {
            int c0 = col0 + wn * 64 + j * 16;
            if (out_sel <= 2) {
                // scatter into [B,H,S,DK]; 16-wide frag never crosses head boundary
                int b = r0 >> 11;           // /SEQ
                int s0 = r0 & (SEQ - 1);
                int h = c0 >> 6;            // /DK
                int d0 = c0 & (DK - 1);
                float* p = out + (((size_t)(b * NHEADS + h) * SEQ + s0) * DK + d0);
                wmma::store_matrix_sync(p, c[i][j], DK, wmma::mem_row_major);
            } else {
                wmma::store_matrix_sync(out + (size_t)r0 * DMODEL + c0, c[i][j], DMODEL,
                                        wmma::mem_row_major);
            }
        }
    }
}

// ---------------- Flash attention (TF32 WMMA), per (b,h, 64-row q tile) ------
// 4 warps; warp w owns rows [w*16, w*16+16). BN tile = 64. d_k = 64.
#define ALD 72                                     // padded leading dim (288B)
#define ATTN_SMEM ((5 * 64 * ALD + 192) * 4)       // 92928 bytes

__global__ void __launch_bounds__(128)
attn_kernel() {
    extern __shared__ __align__(128) float sm[];
    float* Qs = sm;                    // 64 x 72
    float* Ks = sm + 1 * 64 * ALD;
    float* Vs = sm + 2 * 64 * ALD;
    float* Ps = sm + 3 * 64 * ALD;     // scores -> probabilities
    float* Os = sm + 4 * 64 * ALD;     // running output
    float* mrow = sm + 5 * 64 * ALD;   // [64]
    float* lrow = mrow + 64;           // [64]
    float* arow = lrow + 64;           // [64]

    const int t = threadIdx.x;
    const int warp = t >> 5;
    const int q0 = blockIdx.x * 64;
    const int bh = blockIdx.y;
    const float* Qg = g_Q + (size_t)bh * SEQ * DK;
    const float* Kg = g_K + (size_t)bh * SEQ * DK;
    const float* Vg = g_V + (size_t)bh * SEQ * DK;

    // load Q tile, zero O, init stats
#pragma unroll
    for (int i = 0; i < 8; i++) {
        int idx = t + i * 128;        // 1024 float4s
        int r = idx >> 4, v = idx & 15;
        *(float4*)(Qs + r * ALD + v * 4) =
            *(const float4*)(Qg + (size_t)(q0 + r) * DK + v * 4);
        *(float4*)(Os + r * ALD + v * 4) = make_float4(0.f, 0.f, 0.f, 0.f);
    }
    if (t < 64) { mrow[t] = -1e30f; lrow[t] = 0.f; }
    __syncthreads();

    const float scale = 0.125f;   // 1/sqrt(64)

    for (int kt = 0; kt < SEQ; kt += 64) {
        // stage K,V tiles
#pragma unroll
        for (int i = 0; i < 8; i++) {
            int idx = t + i * 128;
            int r = idx >> 4, v = idx & 15;
            *(float4*)(Ks + r * ALD + v * 4) =
                *(const float4*)(Kg + (size_t)(kt + r) * DK + v * 4);
            *(float4*)(Vs + r * ALD + v * 4) =
                *(const float4*)(Vg + (size_t)(kt + r) * DK + v * 4);
        }
        __syncthreads();

        // S = scale * Q @ K^T  (warp: 16 rows x 64 cols)
        {
            wmma::fragment<wmma::accumulator, 16, 16, 8, float> s[4];
#pragma unroll
            for (int j = 0; j < 4; j++) wmma::fill_fragment(s[j], 0.f);
#pragma unroll
            for (int ks = 0; ks < 8; ks++) {
                wmma::fragment<wmma::matrix_a, 16, 16, 8, wmma::precision::tf32, wmma::row_major> a;
                wmma::load_matrix_sync(a, Qs + warp * 16 * ALD + ks * 8, ALD);
#pragma unroll
                for (int e = 0; e < a.num_elements; e++) a.x[e] = wmma::__float_to_tf32(a.x[e]);
#pragma unroll
                for (int j = 0; j < 4; j++) {
                    wmma::fragment<wmma::matrix_b, 16, 16, 8, wmma::precision::tf32, wmma::col_major> b;
                    wmma::load_matrix_sync(b, Ks + (j * 16) * ALD + ks * 8, ALD);
#pragma unroll
                    for (int e = 0; e < b.num_elements; e++) b.x[e] = wmma::__float_to_tf32(b.x[e]);
                    wmma::mma_sync(s[j], a, b, s[j]);
                }
            }
#pragma unroll
            for (int j = 0; j < 4; j++) {
#pragma unroll
                for (int e = 0; e < s[j].num_elements; e++) s[j].x[e] *= scale;
                wmma::store_matrix_sync(Ps + warp * 16 * ALD + j * 16, s[j], ALD,
                                        wmma::mem_row_major);
            }
        }
        __syncthreads();

        // online softmax: 2 threads per row, 32 cols each
        {
            int r = t >> 1, half = t & 1;
            float* Pr = Ps + r * ALD + half * 32;
            float mx = -1e30f;
#pragma unroll
            for (int c = 0; c < 32; c++) mx = fmaxf(mx, Pr[c]);
            mx = fmaxf(mx, __shfl_xor_sync(0xffffffffu, mx, 1));
            float m_new = fmaxf(mrow[r], mx);
            float sum = 0.f;
#pragma unroll
            for (int c = 0; c < 32; c++) {
                float p = __expf(Pr[c] - m_new);
                Pr[c] = p;
                sum += p;
            }
            sum += __shfl_xor_sync(0xffffffffu, sum, 1);
            if (half == 0) {
                float al = __expf(mrow[r] - m_new);
                lrow[r] = lrow[r] * al + sum;
                mrow[r] = m_new;
                arow[r] = al;
            }
        }
        __syncthreads();

        // rescale O by alpha
#pragma unroll
        for (int i = 0; i < 8; i++) {
            int idx = t + i * 128;
            int r = idx >> 4, v = idx & 15;
            float a = arow[r];
            float4* p = (float4*)(Os + r * ALD + v * 4);
            float4 o = *p;
            o.x *= a; o.y *= a; o.z *= a; o.w *= a;
            *p = o;
        }
        __syncthreads();

        // O += P @ V
        {
            wmma::fragment<wmma::accumulator, 16, 16, 8, float> o[4];
#pragma unroll
            for (int j = 0; j < 4; j++)
                wmma::load_matrix_sync(o[j], Os + warp * 16 * ALD + j * 16, ALD,
                                       wmma::mem_row_major);
#pragma unroll
            for (int ks = 0; ks < 8; ks++) {
                wmma::fragment<wmma::matrix_a, 16, 16, 8, wmma::precision::tf32, wmma::row_major> a;
                wmma::load_matrix_sync(a, Ps + warp * 16 * ALD + ks * 8, ALD);
#pragma unroll
                for (int e = 0; e < a.num_elements; e++) a.x[e] = wmma::__float_to_tf32(a.x[e]);
#pragma unroll
                for (int j = 0; j < 4; j++) {
                    wmma::fragment<wmma::matrix_b, 16, 16, 8, wmma::precision::tf32, wmma::row_major> b;
                    wmma::load_matrix_sync(b, Vs + ks * 8 * ALD + j * 16, ALD);
#pragma unroll
                    for (int e = 0; e < b.num_elements; e++) b.x[e] = wmma::__float_to_tf32(b.x[e]);
                    wmma::mma_sync(o[j], a, b, o[j]);
                }
            }
#pragma unroll
            for (int j = 0; j < 4; j++)
                wmma::store_matrix_sync(Os + warp * 16 * ALD + j * 16, o[j], ALD,
                                        wmma::mem_row_major);
        }
        __syncthreads();
    }

    // epilogue: ctx[b, q0+r, h*64+c] = Os[r][c] / l[r]
    const int b = bh >> 4, h = bh & 15;
#pragma unroll
    for (int i = 0; i < 8; i++) {
        int idx = t + i * 128;
        int r = idx >> 4, v = idx & 15;
        float inv = 1.f / lrow[r];
        float4 o = *(float4*)(Os + r * ALD + v * 4);
        o.x *= inv; o.y *= inv; o.z *= inv; o.w *= inv;
        *(float4*)(g_ctx + ((size_t)(b * SEQ + q0 + r) * DMODEL + h * DK + v * 4)) = o;
    }
}

// ---------------- residual + LayerNorm ---------------------------------------
__global__ void __launch_bounds__(256)
ln_kernel(const float* __restrict__ residual, const float* __restrict__ gamma,
          const float* __restrict__ beta, float* __restrict__ out) {
    const int row = blockIdx.x;
    const int t = threadIdx.x;
    const size_t base = (size_t)row * DMODEL + t * 4;

    float4 r4 = *(const float4*)(residual + base);
    float4 p4 = *(const float4*)(g_proj + base);
    float x0 = r4.x + p4.x, x1 = r4.y + p4.y, x2 = r4.z + p4.z, x3 = r4.w + p4.w;

    float s = x0 + x1 + x2 + x3;
    float ss = x0 * x0 + x1 * x1 + x2 * x2 + x3 * x3;
#pragma unroll
    for (int off = 16; off > 0; off >>= 1) {
        s += __shfl_xor_sync(0xffffffffu, s, off);
        ss += __shfl_xor_sync(0xffffffffu, ss, off);
    }
    __shared__ float rs[8], rss[8], stat[2];
    int w = t >> 5, lane = t & 31;
    if (lane == 0) { rs[w] = s; rss[w] = ss; }
    __syncthreads();
    if (t == 0) {
        float S = 0.f, SS = 0.f;
#pragma unroll
        for (int i = 0; i < 8; i++) { S += rs[i]; SS += rss[i]; }
        float mean = S * (1.f / DMODEL);
        float var = SS * (1.f / DMODEL) - mean * mean;
        stat[0] = mean;
        stat[1] = rsqrtf(var + 1e-5f);
    }
    __syncthreads();
    float mean = stat[0], inv = stat[1];

    float4 g4 = *(const float4*)(gamma + t * 4);
    float4 b4 = *(const float4*)(beta + t * 4);
    float4 y;
    y.x = (x0 - mean) * inv * g4.x + b4.x;
    y.y = (x1 - mean) * inv * g4.y + b4.y;
    y.z = (x2 - mean) * inv * g4.z + b4.z;
    y.w = (x3 - mean) * inv * g4.w + b4.w;
    *(float4*)(out + base) = y;
}

// ---------------- launch ------------------------------------------------------
extern "C" void kernel_launch(void* const* d_in, const int* in_sizes, int n_in,
                              void* d_out, int out_size) {
    const float* query = (const float*)d_in[0];
    const float* key   = (const float*)d_in[1];
    const float* value = (const float*)d_in[2];
    const float* Wq    = (const float*)d_in[3];
    const float* bq    = (const float*)d_in[4];
    const float* Wk    = (const float*)d_in[5];
    const float* bk    = (const float*)d_in[6];
    const float* Wv    = (const float*)d_in[7];
    const float* bv    = (const float*)d_in[8];
    const float* Wo    = (const float*)d_in[9];
    const float* bo    = (const float*)d_in[10];
    const float* gamma = (const float*)d_in[11];
    const float* beta  = (const float*)d_in[12];
    float* out = (float*)d_out;

    // idempotent, capture-safe (no allocation, no sync); done every call so the
    // captured graph never depends on prior host state.
    static bool attr_done = false;
    if (!attr_done) {
        (void)cudaFuncSetAttribute(attn_kernel,
                                   cudaFuncAttributeMaxDynamicSharedMemorySize, ATTN_SMEM);
        attr_done = true;
    }

    fill_bias_rep<<<256, 256>>>(bq, bk, bv, bo);

    dim3 ggrid(DMODEL / GBN, MTOT / GBM);   // (8, 64)
    gemm_tf32<<<ggrid, 256>>>(query, Wq, 0, 0, 0);
    gemm_tf32<<<ggrid, 256>>>(key,   Wk, 1, 1, 0);
    gemm_tf32<<<ggrid, 256>>>(value, Wv, 2, 2, 0);

    dim3 agrid(SEQ / 64, BATCH * NHEADS);   // (32, 64)
    attn_kernel<<<agrid, 128, ATTN_SMEM>>>();

    gemm_tf32<<<ggrid, 256>>>(nullptr, Wo, 3, 3, 1);

    ln_kernel<<<MTOT, 256>>>(query, gamma, beta, out);
}

// round 5
// speedup vs baseline: 2.5725x; 2.5725x over previous
#include <cuda_runtime.h>
#include <cuda_bf16.h>
#include <mma.h>

using namespace nvcuda;

// Problem constants
#define BATCH 4
#define SEQ 2048
#define DMODEL 1024
#define NHEADS 16
#define DK 64
#define MTOT (BATCH * SEQ)   // 8192

// ---------------- scratch (static device globals; no runtime allocation) ----
__device__ float g_Q[BATCH * NHEADS * SEQ * DK];       // [B,H,S,DK] f32
__device__ float g_K[BATCH * NHEADS * SEQ * DK];
__device__ float g_V[BATCH * NHEADS * SEQ * DK];
__device__ __nv_bfloat16 g_ctxb[MTOT * DMODEL];        // attention output, bf16
__device__ float g_proj[MTOT * DMODEL];                // ctx @ Wo + bo (f32)
__device__ float g_bias_rep[4 * 16 * DMODEL];          // biases replicated to 16 rows

// ---------------- bias replication --------------------------------------------
__global__ void fill_bias_rep(const float* __restrict__ bq, const float* __restrict__ bk,
                              const float* __restrict__ bv, const float* __restrict__ bo) {
    int idx = blockIdx.x * blockDim.x + threadIdx.x;   // 4*16*1024 = 65536
    if (idx >= 4 * 16 * DMODEL) return;
    int which = idx >> 14;
    int n = idx & (DMODEL - 1);
    const float* src = (which == 0) ? bq : (which == 1) ? bk : (which == 2) ? bv : bo;
    g_bias_rep[idx] = src[n];
}

// ---------------- bf16 WMMA GEMM: C[M,N] = A[M,K] @ W[K,N] + bias -------------
// BM=128, BN=128, BK=64; 8 warps as 4(M) x 2(N); warp tile 32x64 = 2x4 frags.
// a_bf16: A comes from g_ctxb (bf16); else from Aext (f32, converted on stage).
// out_sel: 0/1/2 -> scatter f32 into g_Q/g_K/g_V as [B,H,S,DK]; 3 -> g_proj.
#define GBM 128
#define GBN 128
#define GBK 64
#define GLDA 72    // bf16 elements per As row (144 B)
#define GLDB 136   // bf16 elements per Bs row (272 B)

__global__ void __launch_bounds__(256, 2)
gemm_bf16(const float* __restrict__ Aext, const float* __restrict__ W,
          int bias_idx, int out_sel, int a_bf16) {
    float* out = (out_sel == 0) ? g_Q : (out_sel == 1) ? g_K : (out_sel == 2) ? g_V : g_proj;
    const float* brep = g_bias_rep + bias_idx * 16 * DMODEL;

    __shared__ __align__(16) __nv_bfloat16 As[GBM * GLDA];
    __shared__ __align__(16) __nv_bfloat16 Bs[GBK * GLDB];

    const int t = threadIdx.x;
    const int warp = t >> 5;
    const int wm = warp >> 1;   // 0..3 (M)
    const int wn = warp & 1;    // 0..1 (N)
    const int row0 = blockIdx.y * GBM;
    const int col0 = blockIdx.x * GBN;

    wmma::fragment<wmma::accumulator, 16, 16, 16, float> c[2][4];
#pragma unroll
    for (int i = 0; i < 2; i++)
#pragma unroll
        for (int j = 0; j < 4; j++)
            wmma::load_matrix_sync(c[i][j], brep + col0 + wn * 64 + j * 16, DMODEL,
                                   wmma::mem_row_major);

    for (int kt = 0; kt < DMODEL; kt += GBK) {
        // ---- stage A: 128 x 64 ----
        if (a_bf16) {
            // 8192 bf16 = 1024 uint4; 4 per thread
#pragma unroll
            for (int i = 0; i < 4; i++) {
                int idx = t + i * 256;
                int r = idx >> 3, v = idx & 7;               // v: 8-bf16 chunk (64/8)
                uint4 val = *(const uint4*)(g_ctxb + (size_t)(row0 + r) * DMODEL + kt + v * 8);
                *(uint4*)(As + r * GLDA + v * 8) = val;
            }
        } else {
            // 8192 f32 = 2048 float4; 8 per thread, convert to bf16
#pragma unroll
            for (int i = 0; i < 8; i++) {
                int idx = t + i * 256;
                int r = idx >> 4, v = idx & 15;              // v: float4 (64/4)
                float4 val = *(const float4*)(Aext + (size_t)(row0 + r) * DMODEL + kt + v * 4);
                __nv_bfloat162 lo = __float22bfloat162_rn(make_float2(val.x, val.y));
                __nv_bfloat162 hi = __float22bfloat162_rn(make_float2(val.z, val.w));
                __nv_bfloat16* p = As + r * GLDA + v * 4;
                *(__nv_bfloat162*)(p)     = lo;
                *(__nv_bfloat162*)(p + 2) = hi;
            }
        }
        // ---- stage B: 64 x 128 (f32 -> bf16) ----
#pragma unroll
        for (int i = 0; i < 8; i++) {
            int idx = t + i * 256;
            int r = idx >> 5, v = idx & 31;                  // v: float4 (128/4)
            float4 val = *(const float4*)(W + (size_t)(kt + r) * DMODEL + col0 + v * 4);
            __nv_bfloat162 lo = __float22bfloat162_rn(make_float2(val.x, val.y));
            __nv_bfloat162 hi = __float22bfloat162_rn(make_float2(val.z, val.w));
            __nv_bfloat16* p = Bs + r * GLDB + v * 4;
            *(__nv_bfloat162*)(p)     = lo;
            *(__nv_bfloat162*)(p + 2) = hi;
        }
        __syncthreads();

#pragma unroll
        for (int ks = 0; ks < GBK / 16; ks++) {
            wmma::fragment<wmma::matrix_a, 16, 16, 16, __nv_bfloat16, wmma::row_major> a[2];
            wmma::fragment<wmma::matrix_b, 16, 16, 16, __nv_bfloat16, wmma::row_major> b[4];
#pragma unroll
            for (int i = 0; i < 2; i++)
                wmma::load_matrix_sync(a[i], As + (wm * 32 + i * 16) * GLDA + ks * 16, GLDA);
#pragma unroll
            for (int j = 0; j < 4; j++)
                wmma::load_matrix_sync(b[j], Bs + ks * 16 * GLDB + wn * 64 + j * 16, GLDB);
#pragma unroll
            for (int i = 0; i < 2; i++)
#pragma unroll
                for (int j = 0; j < 4; j++)
                    wmma::mma_sync(c[i][j], a[i], b[j], c[i][j]);
        }
        __syncthreads();
    }

    // epilogue (f32 stores)
#pragma unroll
    for (int i = 0; i < 2; i++) {
        int r0 = row0 + wm * 32 + i * 16;
#pragma unroll
        for (int j = 0; j < 4; j++) {
            int c0 = col0 + wn * 64 + j * 16;
            if (out_sel <= 2) {
                int b = r0 >> 11;           // /SEQ
                int s0 = r0 & (SEQ - 1);
                int h = c0 >> 6;            // /DK
                int d0 = c0 & (DK - 1);
                float* p = out + (((size_t)(b * NHEADS + h) * SEQ + s0) * DK + d0);
                wmma::store_matrix_sync(p, c[i][j], DK, wmma::mem_row_major);
            } else {
                wmma::store_matrix_sync(out + (size_t)r0 * DMODEL + c0, c[i][j], DMODEL,
                                        wmma::mem_row_major);
            }
        }
    }
}

// ---------------- Flash attention (bf16 WMMA), 128-row q tile -----------------
// 256 threads = 8 warps; warp w owns q-rows [w*16, w*16+16). K tile = 64. dk=64.
// O accumulator lives in registers: thread (r=t>>1, half=t&1) owns O[r][half*32..+32].
#define QT 128
#define KT 64
#define ALDH 72     // bf16 leading dim (Qs/Ks/Vs/Pb)
#define ALDF 68     // f32 leading dim (Ps)
#define ATTN_SMEM ((QT*ALDH + KT*ALDH + KT*ALDH + QT*ALDH) * 2 + QT*ALDF*4 + 3*QT*4)

__global__ void __launch_bounds__(256, 2)
attn_kernel() {
    extern __shared__ __align__(16) char smraw[];
    __nv_bfloat16* Qs = (__nv_bfloat16*)smraw;            // 128 x 72
    __nv_bfloat16* Ks = Qs + QT * ALDH;                   // 64 x 72
    __nv_bfloat16* Vs = Ks + KT * ALDH;                   // 64 x 72
    __nv_bfloat16* Pb = Vs + KT * ALDH;                   // 128 x 72 (bf16 probs)
    float* Ps  = (float*)(Pb + QT * ALDH);                // 128 x 68 (f32 scores / PV partials)
    float* mrow = Ps + QT * ALDF;                          // [128]
    float* lrow = mrow + QT;
    float* arow = lrow + QT;

    const int t = threadIdx.x;
    const int warp = t >> 5;
    const int q0 = blockIdx.x * QT;
    const int bh = blockIdx.y;
    const float* Qg = g_Q + (size_t)bh * SEQ * DK;
    const float* Kg = g_K + (size_t)bh * SEQ * DK;
    const float* Vg = g_V + (size_t)bh * SEQ * DK;

    // load Q tile (f32 -> bf16): 128x16 float4 = 2048, 8 per thread
#pragma unroll
    for (int i = 0; i < 8; i++) {
        int idx = t + i * 256;
        int r = idx >> 4, v = idx & 15;
        float4 val = *(const float4*)(Qg + (size_t)(q0 + r) * DK + v * 4);
        __nv_bfloat16* p = Qs + r * ALDH + v * 4;
        *(__nv_bfloat162*)(p)     = __float22bfloat162_rn(make_float2(val.x, val.y));
        *(__nv_bfloat162*)(p + 2) = __float22bfloat162_rn(make_float2(val.z, val.w));
    }
    if (t < QT) { mrow[t] = -1e30f; lrow[t] = 0.f; }

    // register-resident O
    const int r = t >> 1;          // 0..127
    const int half = t & 1;        // 0/1
    float Oa[32];
#pragma unroll
    for (int c = 0; c < 32; c++) Oa[c] = 0.f;

    const float scale = 0.125f;    // 1/sqrt(64)

    for (int kt = 0; kt < SEQ; kt += KT) {
        // stage K,V (f32 -> bf16): 2 * 64x16 float4 = 2048, 8 per thread
#pragma unroll
        for (int i = 0; i < 4; i++) {
            int idx = t + i * 256;
            int rr = idx >> 4, v = idx & 15;
            float4 kv = *(const float4*)(Kg + (size_t)(kt + rr) * DK + v * 4);
            __nv_bfloat16* p = Ks + rr * ALDH + v * 4;
            *(__nv_bfloat162*)(p)     = __float22bfloat162_rn(make_float2(kv.x, kv.y));
            *(__nv_bfloat162*)(p + 2) = __float22bfloat162_rn(make_float2(kv.z, kv.w));
            float4 vv = *(const float4*)(Vg + (size_t)(kt + rr) * DK + v * 4);
            __nv_bfloat16* q = Vs + rr * ALDH + v * 4;
            *(__nv_bfloat162*)(q)     = __float22bfloat162_rn(make_float2(vv.x, vv.y));
            *(__nv_bfloat162*)(q + 2) = __float22bfloat162_rn(make_float2(vv.z, vv.w));
        }
        __syncthreads();   // (A) KV ready; prior merge finished reading Ps

        // S = scale * Q @ K^T : warp computes 16 x 64
        {
            wmma::fragment<wmma::accumulator, 16, 16, 16, float> s[4];
#pragma unroll
            for (int j = 0; j < 4; j++) wmma::fill_fragment(s[j], 0.f);
#pragma unroll
            for (int ks = 0; ks < 4; ks++) {
                wmma::fragment<wmma::matrix_a, 16, 16, 16, __nv_bfloat16, wmma::row_major> a;
                wmma::load_matrix_sync(a, Qs + warp * 16 * ALDH + ks * 16, ALDH);
#pragma unroll
                for (int j = 0; j < 4; j++) {
                    wmma::fragment<wmma::matrix_b, 16, 16, 16, __nv_bfloat16, wmma::col_major> b;
                    wmma::load_matrix_sync(b, Ks + (j * 16) * ALDH + ks * 16, ALDH);
                    wmma::mma_sync(s[j], a, b, s[j]);
                }
            }
#pragma unroll
            for (int j = 0; j < 4; j++) {
#pragma unroll
                for (int e = 0; e < s[j].num_elements; e++) s[j].x[e] *= scale;
                wmma::store_matrix_sync(Ps + warp * 16 * ALDF + j * 16, s[j], ALDF,
                                        wmma::mem_row_major);
            }
        }
        __syncthreads();   // (B) scores in Ps

        // online softmax: thread owns (r, cols half*32..+32)
        {
            float sc[32];
            const float* Pr = Ps + r * ALDF + half * 32;
            float mx = -1e30f;
#pragma unroll
            for (int c = 0; c < 32; c++) { sc[c] = Pr[c]; mx = fmaxf(mx, sc[c]); }
            mx = fmaxf(mx, __shfl_xor_sync(0xffffffffu, mx, 1));
            float m_new = fmaxf(mrow[r], mx);
            float sum = 0.f;
#pragma unroll
            for (int c = 0; c < 32; c++) { sc[c] = __expf(sc[c] - m_new); sum += sc[c]; }
            sum += __shfl_xor_sync(0xffffffffu, sum, 1);
            __nv_bfloat16* Pw = Pb + r * ALDH + half * 32;
#pragma unroll
            for (int c = 0; c < 16; c++)
                *(__nv_bfloat162*)(Pw + 2 * c) =
                    __float22bfloat162_rn(make_float2(sc[2 * c], sc[2 * c + 1]));
            if (half == 0) {
                float al = __expf(mrow[r] - m_new);
                lrow[r] = lrow[r] * al + sum;
                mrow[r] = m_new;
                arow[r] = al;
            }
        }
        __syncthreads();   // (C) Pb + alpha ready

        // PV partial: warp computes 16 x 64 into Ps (f32)
        {
            wmma::fragment<wmma::accumulator, 16, 16, 16, float> o4[4];
#pragma unroll
            for (int j = 0; j < 4; j++) wmma::fill_fragment(o4[j], 0.f);
#pragma unroll
            for (int ks = 0; ks < 4; ks++) {
                wmma::fragment<wmma::matrix_a, 16, 16, 16, __nv_bfloat16, wmma::row_major> a;
                wmma::load_matrix_sync(a, Pb + warp * 16 * ALDH + ks * 16, ALDH);
#pragma unroll
                for (int j = 0; j < 4; j++) {
                    wmma::fragment<wmma::matrix_b, 16, 16, 16, __nv_bfloat16, wmma::row_major> b;
                    wmma::load_matrix_sync(b, Vs + (ks * 16) * ALDH + j * 16, ALDH);
                    wmma::mma_sync(o4[j], a, b, o4[j]);
                }
            }
#pragma unroll
            for (int j = 0; j < 4; j++)
                wmma::store_matrix_sync(Ps + warp * 16 * ALDF + j * 16, o4[j], ALDF,
                                        wmma::mem_row_major);
        }
        __syncthreads();   // (D) PV partials in Ps

        // merge into register O: O = alpha*O + PV
        {
            float al = arow[r];
            const float* Pv = Ps + r * ALDF + half * 32;
#pragma unroll
            for (int c = 0; c < 32; c++) Oa[c] = al * Oa[c] + Pv[c];
        }
        // next iteration's sync (A) orders this read before Ps is rewritten
    }

    // epilogue: ctx[b, q0+r, h*64 + half*32 + c] = O[c] / l[r]   (bf16)
    const int b = bh >> 4, h = bh & 15;
    {
        float inv = 1.f / lrow[r];
        __nv_bfloat16* dst = g_ctxb + ((size_t)(b * SEQ + q0 + r) * DMODEL + h * DK + half * 32);
#pragma unroll
        for (int c = 0; c < 16; c++)
            *(__nv_bfloat162*)(dst + 2 * c) =
                __float22bfloat162_rn(make_float2(Oa[2 * c] * inv, Oa[2 * c + 1] * inv));
    }
}

// ---------------- residual + LayerNorm ---------------------------------------
__global__ void __launch_bounds__(256)
ln_kernel(const float* __restrict__ residual, const float* __restrict__ gamma,
          const float* __restrict__ beta, float* __restrict__ out) {
    const int row = blockIdx.x;
    const int t = threadIdx.x;
    const size_t base = (size_t)row * DMODEL + t * 4;

    float4 r4 = *(const float4*)(residual + base);
    float4 p4 = *(const float4*)(g_proj + base);
    float x0 = r4.x + p4.x, x1 = r4.y + p4.y, x2 = r4.z + p4.z, x3 = r4.w + p4.w;

    float s = x0 + x1 + x2 + x3;
    float ss = x0 * x0 + x1 * x1 + x2 * x2 + x3 * x3;
#pragma unroll
    for (int off = 16; off > 0; off >>= 1) {
        s += __shfl_xor_sync(0xffffffffu, s, off);
        ss += __shfl_xor_sync(0xffffffffu, ss, off);
    }
    __shared__ float rs[8], rss[8], stat[2];
    int w = t >> 5, lane = t & 31;
    if (lane == 0) { rs[w] = s; rss[w] = ss; }
    __syncthreads();
    if (t == 0) {
        float S = 0.f, SS = 0.f;
#pragma unroll
        for (int i = 0; i < 8; i++) { S += rs[i]; SS += rss[i]; }
        float mean = S * (1.f / DMODEL);
        float var = SS * (1.f / DMODEL) - mean * mean;
        stat[0] = mean;
        stat[1] = rsqrtf(var + 1e-5f);
    }
    __syncthreads();
    float mean = stat[0], inv = stat[1];

    float4 g4 = *(const float4*)(gamma + t * 4);
    float4 b4 = *(const float4*)(beta + t * 4);
    float4 y;
    y.x = (x0 - mean) * inv * g4.x + b4.x;
    y.y = (x1 - mean) * inv * g4.y + b4.y;
    y.z = (x2 - mean) * inv * g4.z + b4.z;
    y.w = (x3 - mean) * inv * g4.w + b4.w;
    *(float4*)(out + base) = y;
}

// ---------------- launch ------------------------------------------------------
extern "C" void kernel_launch(void* const* d_in, const int* in_sizes, int n_in,
                              void* d_out, int out_size) {
    const float* query = (const float*)d_in[0];
    const float* key   = (const float*)d_in[1];
    const float* value = (const float*)d_in[2];
    const float* Wq    = (const float*)d_in[3];
    const float* bq    = (const float*)d_in[4];
    const float* Wk    = (const float*)d_in[5];
    const float* bk    = (const float*)d_in[6];
    const float* Wv    = (const float*)d_in[7];
    const float* bv    = (const float*)d_in[8];
    const float* Wo    = (const float*)d_in[9];
    const float* bo    = (const float*)d_in[10];
    const float* gamma = (const float*)d_in[11];
    const float* beta  = (const float*)d_in[12];
    float* out = (float*)d_out;

    static bool attr_done = false;
    if (!attr_done) {
        (void)cudaFuncSetAttribute(attn_kernel,
                                   cudaFuncAttributeMaxDynamicSharedMemorySize, ATTN_SMEM);
        attr_done = true;
    }

    fill_bias_rep<<<256, 256>>>(bq, bk, bv, bo);

    dim3 ggrid(DMODEL / GBN, MTOT / GBM);   // (8, 64)
    gemm_bf16<<<ggrid, 256>>>(query, Wq, 0, 0, 0);
    gemm_bf16<<<ggrid, 256>>>(key,   Wk, 1, 1, 0);
    gemm_bf16<<<ggrid, 256>>>(value, Wv, 2, 2, 0);

    dim3 agrid(SEQ / QT, BATCH * NHEADS);   // (16, 64)
    attn_kernel<<<agrid, 256, ATTN_SMEM>>>();

    gemm_bf16<<<ggrid, 256>>>(nullptr, Wo, 3, 3, 1);

    ln_kernel<<<MTOT, 256>>>(query, gamma, beta, out);
}

// round 7
// speedup vs baseline: 2.8278x; 1.0992x over previous
#include <cuda_runtime.h>
#include <cuda_bf16.h>
#include <mma.h>
#include <cstdint>

using namespace nvcuda;

#define BATCH 4
#define SEQ 2048
#define DMODEL 1024
#define NHEADS 16
#define DK 64
#define MTOT (BATCH * SEQ)   // 8192

// ---------------- scratch ----------------------------------------------------
__device__ __nv_bfloat16 g_xb[MTOT * DMODEL];     // query (bf16)
__device__ __nv_bfloat16 g_kb[MTOT * DMODEL];     // key   (bf16)
__device__ __nv_bfloat16 g_vb[MTOT * DMODEL];     // value (bf16)
__device__ __nv_bfloat16 g_Wqb[DMODEL * DMODEL];
__device__ __nv_bfloat16 g_Wkb[DMODEL * DMODEL];
__device__ __nv_bfloat16 g_Wvb[DMODEL * DMODEL];
__device__ __nv_bfloat16 g_Wob[DMODEL * DMODEL];
__device__ __nv_bfloat16 g_Qb[BATCH * NHEADS * SEQ * DK];   // [B,H,S,DK] bf16
__device__ __nv_bfloat16 g_Kb[BATCH * NHEADS * SEQ * DK];
__device__ __nv_bfloat16 g_Vb[BATCH * NHEADS * SEQ * DK];
__device__ __nv_bfloat16 g_ctxb[MTOT * DMODEL];             // attention out bf16
__device__ float g_proj[MTOT * DMODEL];                     // ctx @ Wo + bo (f32)
__device__ float g_bias_rep[4 * 16 * DMODEL];

// ---------------- f32 -> bf16 convert ----------------------------------------
__global__ void __launch_bounds__(256)
f2b_kernel(const float* __restrict__ src, __nv_bfloat16* __restrict__ dst, int n4) {
    int i = blockIdx.x * blockDim.x + threadIdx.x;
    if (i >= n4) return;
    float4 v = ((const float4*)src)[i];
    ((__nv_bfloat162*)dst)[2 * i]     = __float22bfloat162_rn(make_float2(v.x, v.y));
    ((__nv_bfloat162*)dst)[2 * i + 1] = __float22bfloat162_rn(make_float2(v.z, v.w));
}

__global__ void fill_bias_rep(const float* __restrict__ bq, const float* __restrict__ bk,
                              const float* __restrict__ bv, const float* __restrict__ bo) {
    int idx = blockIdx.x * blockDim.x + threadIdx.x;
    if (idx >= 4 * 16 * DMODEL) return;
    int which = idx >> 14;
    int n = idx & (DMODEL - 1);
    const float* src = (which == 0) ? bq : (which == 1) ? bk : (which == 2) ? bv : bo;
    g_bias_rep[idx] = src[n];
}

// ---------------- cp.async helpers -------------------------------------------
__device__ __forceinline__ void cp_async16(void* smem_dst, const void* gmem_src) {
    unsigned int a = (unsigned int)__cvta_generic_to_shared(smem_dst);
    asm volatile("cp.async.cg.shared.global [%0], [%1], 16;\n" :: "r"(a), "l"(gmem_src));
}
#define CP_COMMIT() asm volatile("cp.async.commit_group;\n" ::: "memory")
#define CP_WAIT0()  asm volatile("cp.async.wait_group 0;\n" ::: "memory")

// ---------------- bf16 GEMM with 2-stage cp.async pipeline --------------------
// C[M,N] = A[M,K] @ W[K,N] + bias.  BM=128,BN=128,BK=64; 8 warps 4(M)x2(N).
// out_sel 0/1/2: bf16 scatter to g_Qb/g_Kb/g_Vb [B,H,S,DK]; 3: f32 g_proj.
#define GBM 128
#define GBN 128
#define GBK 64
#define GLDA 72      // bf16/row (144B, 16B mult)
#define GLDB 136     // bf16/row (272B, 16B mult)
#define GEMM_SMEM (2 * (GBM * GLDA + GBK * GLDB) * 2)   // 71680 B
#define NKT (DMODEL / GBK)                              // 16

__global__ void __launch_bounds__(256, 2)
gemm_bf16(const __nv_bfloat16* __restrict__ A, const __nv_bfloat16* __restrict__ W,
          int bias_idx, int out_sel) {
    extern __shared__ __align__(16) char smraw[];
    __nv_bfloat16* As[2] = { (__nv_bfloat16*)smraw,
                             (__nv_bfloat16*)smraw + GBM * GLDA };
    __nv_bfloat16* Bs[2] = { (__nv_bfloat16*)smraw + 2 * GBM * GLDA,
                             (__nv_bfloat16*)smraw + 2 * GBM * GLDA + GBK * GLDB };

    const int t = threadIdx.x;
    const int warp = t >> 5;
    const int wm = warp >> 1;
    const int wn = warp & 1;
    const int row0 = blockIdx.y * GBM;
    const int col0 = blockIdx.x * GBN;
    const float* brep = g_bias_rep + bias_idx * 16 * DMODEL;

    wmma::fragment<wmma::accumulator, 16, 16, 16, float> c[2][4];
#pragma unroll
    for (int i = 0; i < 2; i++)
#pragma unroll
        for (int j = 0; j < 4; j++)
            wmma::load_matrix_sync(c[i][j], brep + col0 + wn * 64 + j * 16, DMODEL,
                                   wmma::mem_row_major);

    // issue tile 0
    {
#pragma unroll
        for (int i = 0; i < 4; i++) {   // A: 1024 chunks of 16B
            int idx = t + i * 256;
            int r = idx >> 3, v = idx & 7;
            cp_async16(As[0] + r * GLDA + v * 8, A + (size_t)(row0 + r) * DMODEL + v * 8);
        }
#pragma unroll
        for (int i = 0; i < 4; i++) {   // B: 1024 chunks of 16B
            int idx = t + i * 256;
            int r = idx >> 4, v = idx & 15;
            cp_async16(Bs[0] + r * GLDB + v * 8, W + (size_t)r * DMODEL + col0 + v * 8);
        }
        CP_COMMIT();
    }

    for (int kt = 0; kt < NKT; kt++) {
        const int buf = kt & 1;
        CP_WAIT0();
        __syncthreads();                 // tile kt visible; other buffer free
        if (kt + 1 < NKT) {
            const int k1 = (kt + 1) * GBK;
#pragma unroll
            for (int i = 0; i < 4; i++) {
                int idx = t + i * 256;
                int r = idx >> 3, v = idx & 7;
                cp_async16(As[buf ^ 1] + r * GLDA + v * 8,
                           A + (size_t)(row0 + r) * DMODEL + k1 + v * 8);
            }
#pragma unroll
            for (int i = 0; i < 4; i++) {
                int idx = t + i * 256;
                int r = idx >> 4, v = idx & 15;
                cp_async16(Bs[buf ^ 1] + r * GLDB + v * 8,
                           W + (size_t)(k1 + r) * DMODEL + col0 + v * 8);
            }
            CP_COMMIT();
        }

#pragma unroll
        for (int ks = 0; ks < GBK / 16; ks++) {
            wmma::fragment<wmma::matrix_a, 16, 16, 16, __nv_bfloat16, wmma::row_major> a[2];
            wmma::fragment<wmma::matrix_b, 16, 16, 16, __nv_bfloat16, wmma::row_major> b[4];
#pragma unroll
            for (int i = 0; i < 2; i++)
                wmma::load_matrix_sync(a[i], As[buf] + (wm * 32 + i * 16) * GLDA + ks * 16, GLDA);
#pragma unroll
            for (int j = 0; j < 4; j++)
                wmma::load_matrix_sync(b[j], Bs[buf] + ks * 16 * GLDB + wn * 64 + j * 16, GLDB);
#pragma unroll
            for (int i = 0; i < 2; i++)
#pragma unroll
                for (int j = 0; j < 4; j++)
                    wmma::mma_sync(c[i][j], a[i], b[j], c[i][j]);
        }
        __syncthreads();                 // all done reading buf before it is refilled
    }

    if (out_sel <= 2) {
        // stage f32 in smem, convert, scatter bf16 to [B,H,S,DK]
        __nv_bfloat16* outb = (out_sel == 0) ? g_Qb : (out_sel == 1) ? g_Kb : g_Vb;
        float* stage = (float*)smraw;    // 128 x 132 (67584 B <= 71680)
#pragma unroll
        for (int i = 0; i < 2; i++)
#pragma unroll
            for (int j = 0; j < 4; j++)
                wmma::store_matrix_sync(stage + (wm * 32 + i * 16) * 132 + wn * 64 + j * 16,
                                        c[i][j], 132, wmma::mem_row_major);
        __syncthreads();
        const int r = t >> 1, hf = t & 1;
        const int gr = row0 + r;
        const int gc = col0 + hf * 64;
        const int b = gr >> 11, s0 = gr & (SEQ - 1), h = gc >> 6;
        __nv_bfloat16* dst = outb + ((size_t)(b * NHEADS + h) * SEQ + s0) * DK;
        const float* src = stage + r * 132 + hf * 64;
#pragma unroll
        for (int v = 0; v < 32; v++)
            *(__nv_bfloat162*)(dst + 2 * v) =
                __float22bfloat162_rn(make_float2(src[2 * v], src[2 * v + 1]));
    } else {
#pragma unroll
        for (int i = 0; i < 2; i++) {
            int r0 = row0 + wm * 32 + i * 16;
#pragma unroll
            for (int j = 0; j < 4; j++)
                wmma::store_matrix_sync(g_proj + (size_t)r0 * DMODEL + col0 + wn * 64 + j * 16,
                                        c[i][j], DMODEL, wmma::mem_row_major);
        }
    }
}

// ---------------- Flash attention (bf16 in, register O) ----------------------
#define QT 128
#define KT 64
#define ALDH 72
#define ALDF 68
#define ATTN_SMEM ((QT*ALDH + KT*ALDH + KT*ALDH + QT*ALDH) * 2 + QT*ALDF*4 + 3*QT*4)

__global__ void __launch_bounds__(256, 2)
attn_kernel() {
    extern __shared__ __align__(16) char smraw[];
    __nv_bfloat16* Qs = (__nv_bfloat16*)smraw;            // 128 x 72
    __nv_bfloat16* Ks = Qs + QT * ALDH;                   // 64 x 72
    __nv_bfloat16* Vs = Ks + KT * ALDH;                   // 64 x 72
    __nv_bfloat16* Pb = Vs + KT * ALDH;                   // 128 x 72
    float* Ps  = (float*)(Pb + QT * ALDH);                // 128 x 68
    float* mrow = Ps + QT * ALDF;
    float* lrow = mrow + QT;
    float* arow = lrow + QT;

    const int t = threadIdx.x;
    const int warp = t >> 5;
    const int q0 = blockIdx.x * QT;
    const int bh = blockIdx.y;
    const __nv_bfloat16* Qg = g_Qb + (size_t)bh * SEQ * DK;
    const __nv_bfloat16* Kg = g_Kb + (size_t)bh * SEQ * DK;
    const __nv_bfloat16* Vg = g_Vb + (size_t)bh * SEQ * DK;

    // load Q tile: 128 rows x 8 uint4 chunks = 1024, 4/thread
#pragma unroll
    for (int i = 0; i < 4; i++) {
        int idx = t + i * 256;
        int r = idx >> 3, v = idx & 7;
        *(uint4*)(Qs + r * ALDH + v * 8) =
            *(const uint4*)(Qg + (size_t)(q0 + r) * DK + v * 8);
    }
    if (t < QT) { mrow[t] = -1e30f; lrow[t] = 0.f; }

    const int r = t >> 1;
    const int half = t & 1;
    float Oa[32];
#pragma unroll
    for (int c = 0; c < 32; c++) Oa[c] = 0.f;

    const float scale = 0.125f;

    for (int kt = 0; kt < SEQ; kt += KT) {
        // stage K,V: 2 * 512 uint4 chunks, 4/thread total
#pragma unroll
        for (int i = 0; i < 2; i++) {
            int idx = t + i * 256;
            int rr = idx >> 3, v = idx & 7;
            *(uint4*)(Ks + rr * ALDH + v * 8) =
                *(const uint4*)(Kg + (size_t)(kt + rr) * DK + v * 8);
            *(uint4*)(Vs + rr * ALDH + v * 8) =
                *(const uint4*)(Vg + (size_t)(kt + rr) * DK + v * 8);
        }
        __syncthreads();   // (A)

        // S = scale * Q @ K^T
        {
            wmma::fragment<wmma::accumulator, 16, 16, 16, float> s[4];
#pragma unroll
            for (int j = 0; j < 4; j++) wmma::fill_fragment(s[j], 0.f);
#pragma unroll
            for (int ks = 0; ks < 4; ks++) {
                wmma::fragment<wmma::matrix_a, 16, 16, 16, __nv_bfloat16, wmma::row_major> a;
                wmma::load_matrix_sync(a, Qs + warp * 16 * ALDH + ks * 16, ALDH);
#pragma unroll
                for (int j = 0; j < 4; j++) {
                    wmma::fragment<wmma::matrix_b, 16, 16, 16, __nv_bfloat16, wmma::col_major> b;
                    wmma::load_matrix_sync(b, Ks + (j * 16) * ALDH + ks * 16, ALDH);
                    wmma::mma_sync(s[j], a, b, s[j]);
                }
            }
#pragma unroll
            for (int j = 0; j < 4; j++) {
#pragma unroll
                for (int e = 0; e < s[j].num_elements; e++) s[j].x[e] *= scale;
                wmma::store_matrix_sync(Ps + warp * 16 * ALDF + j * 16, s[j], ALDF,
                                        wmma::mem_row_major);
            }
        }
        __syncthreads();   // (B)

        // online softmax
        {
            float sc[32];
            const float* Pr = Ps + r * ALDF + half * 32;
            float mx = -1e30f;
#pragma unroll
            for (int c = 0; c < 32; c++) { sc[c] = Pr[c]; mx = fmaxf(mx, sc[c]); }
            mx = fmaxf(mx, __shfl_xor_sync(0xffffffffu, mx, 1));
            float m_new = fmaxf(mrow[r], mx);
            float sum = 0.f;
#pragma unroll
            for (int c = 0; c < 32; c++) { sc[c] = __expf(sc[c] - m_new); sum += sc[c]; }
            sum += __shfl_xor_sync(0xffffffffu, sum, 1);
            __nv_bfloat16* Pw = Pb + r * ALDH + half * 32;
#pragma unroll
            for (int c = 0; c < 16; c++)
                *(__nv_bfloat162*)(Pw + 2 * c) =
                    __float22bfloat162_rn(make_float2(sc[2 * c], sc[2 * c + 1]));
            if (half == 0) {
                float al = __expf(mrow[r] - m_new);
                lrow[r] = lrow[r] * al + sum;
                mrow[r] = m_new;
                arow[r] = al;
            }
        }
        __syncthreads();   // (C)

        // PV partial
        {
            wmma::fragment<wmma::accumulator, 16, 16, 16, float> o4[4];
#pragma unroll
            for (int j = 0; j < 4; j++) wmma::fill_fragment(o4[j], 0.f);
#pragma unroll
            for (int ks = 0; ks < 4; ks++) {
                wmma::fragment<wmma::matrix_a, 16, 16, 16, __nv_bfloat16, wmma::row_major> a;
                wmma::load_matrix_sync(a, Pb + warp * 16 * ALDH + ks * 16, ALDH);
#pragma unroll
                for (int j = 0; j < 4; j++) {
                    wmma::fragment<wmma::matrix_b, 16, 16, 16, __nv_bfloat16, wmma::row_major> b;
                    wmma::load_matrix_sync(b, Vs + (ks * 16) * ALDH + j * 16, ALDH);
                    wmma::mma_sync(o4[j], a, b, o4[j]);
                }
            }
#pragma unroll
            for (int j = 0; j < 4; j++)
                wmma::store_matrix_sync(Ps + warp * 16 * ALDF + j * 16, o4[j], ALDF,
                                        wmma::mem_row_major);
        }
        __syncthreads();   // (D)

        // merge
        {
            float al = arow[r];
            const float* Pv = Ps + r * ALDF + half * 32;
#pragma unroll
            for (int c = 0; c < 32; c++) Oa[c] = al * Oa[c] + Pv[c];
        }
    }

    const int b = bh >> 4, h = bh & 15;
    {
        float inv = 1.f / lrow[r];
        __nv_bfloat16* dst = g_ctxb + ((size_t)(b * SEQ + q0 + r) * DMODEL + h * DK + half * 32);
#pragma unroll
        for (int c = 0; c < 16; c++)
            *(__nv_bfloat162*)(dst + 2 * c) =
                __float22bfloat162_rn(make_float2(Oa[2 * c] * inv, Oa[2 * c + 1] * inv));
    }
}

// ---------------- residual + LayerNorm ---------------------------------------
__global__ void __launch_bounds__(256)
ln_kernel(const float* __restrict__ residual, const float* __restrict__ gamma,
          const float* __restrict__ beta, float* __restrict__ out) {
    const int row = blockIdx.x;
    const int t = threadIdx.x;
    const size_t base = (size_t)row * DMODEL + t * 4;

    float4 r4 = *(const float4*)(residual + base);
    float4 p4 = *(const float4*)(g_proj + base);
    float x0 = r4.x + p4.x, x1 = r4.y + p4.y, x2 = r4.z + p4.z, x3 = r4.w + p4.w;

    float s = x0 + x1 + x2 + x3;
    float ss = x0 * x0 + x1 * x1 + x2 * x2 + x3 * x3;
#pragma unroll
    for (int off = 16; off > 0; off >>= 1) {
        s += __shfl_xor_sync(0xffffffffu, s, off);
        ss += __shfl_xor_sync(0xffffffffu, ss, off);
    }
    __shared__ float rs[8], rss[8], stat[2];
    int w = t >> 5, lane = t & 31;
    if (lane == 0) { rs[w] = s; rss[w] = ss; }
    __syncthreads();
    if (t == 0) {
        float S = 0.f, SS = 0.f;
#pragma unroll
        for (int i = 0; i < 8; i++) { S += rs[i]; SS += rss[i]; }
        float mean = S * (1.f / DMODEL);
        float var = SS * (1.f / DMODEL) - mean * mean;
        stat[0] = mean;
        stat[1] = rsqrtf(var + 1e-5f);
    }
    __syncthreads();
    float mean = stat[0], inv = stat[1];

    float4 g4 = *(const float4*)(gamma + t * 4);
    float4 b4 = *(const float4*)(beta + t * 4);
    float4 y;
    y.x = (x0 - mean) * inv * g4.x + b4.x;
    y.y = (x1 - mean) * inv * g4.y + b4.y;
    y.z = (x2 - mean) * inv * g4.z + b4.z;
    y.w = (x3 - mean) * inv * g4.w + b4.w;
    *(float4*)(out + base) = y;
}

// ---------------- launch ------------------------------------------------------
extern "C" void kernel_launch(void* const* d_in, const int* in_sizes, int n_in,
                              void* d_out, int out_size) {
    const float* query = (const float*)d_in[0];
    const float* key   = (const float*)d_in[1];
    const float* value = (const float*)d_in[2];
    const float* Wq    = (const float*)d_in[3];
    const float* bq    = (const float*)d_in[4];
    const float* Wk    = (const float*)d_in[5];
    const float* bk    = (const float*)d_in[6];
    const float* Wv    = (const float*)d_in[7];
    const float* bv    = (const float*)d_in[8];
    const float* Wo    = (const float*)d_in[9];
    const float* bo    = (const float*)d_in[10];
    const float* gamma = (const float*)d_in[11];
    const float* beta  = (const float*)d_in[12];
    float* out = (float*)d_out;

    static bool attr_done = false;
    if (!attr_done) {
        (void)cudaFuncSetAttribute(attn_kernel,
                                   cudaFuncAttributeMaxDynamicSharedMemorySize, ATTN_SMEM);
        (void)cudaFuncSetAttribute(gemm_bf16,
                                   cudaFuncAttributeMaxDynamicSharedMemorySize, GEMM_SMEM);
        attr_done = true;
    }

    // resolve device-global addresses (host side; capture-safe)
    static __nv_bfloat16 *xb = nullptr, *kb, *vb, *wqb, *wkb, *wvb, *wob, *ctxb;
    if (!xb) {
        cudaGetSymbolAddress((void**)&xb,   g_xb);
        cudaGetSymbolAddress((void**)&kb,   g_kb);
        cudaGetSymbolAddress((void**)&vb,   g_vb);
        cudaGetSymbolAddress((void**)&wqb,  g_Wqb);
        cudaGetSymbolAddress((void**)&wkb,  g_Wkb);
        cudaGetSymbolAddress((void**)&wvb,  g_Wvb);
        cudaGetSymbolAddress((void**)&wob,  g_Wob);
        cudaGetSymbolAddress((void**)&ctxb, g_ctxb);
    }

    const int n4_act = MTOT * DMODEL / 4;     // 2097152
    const int n4_w   = DMODEL * DMODEL / 4;   // 262144
    f2b_kernel<<<n4_act / 256, 256>>>(query, xb, n4_act);
    f2b_kernel<<<n4_act / 256, 256>>>(key,   kb, n4_act);
    f2b_kernel<<<n4_act / 256, 256>>>(value, vb, n4_act);
    f2b_kernel<<<n4_w / 256, 256>>>(Wq, wqb, n4_w);
    f2b_kernel<<<n4_w / 256, 256>>>(Wk, wkb, n4_w);
    f2b_kernel<<<n4_w / 256, 256>>>(Wv, wvb, n4_w);
    f2b_kernel<<<n4_w / 256, 256>>>(Wo, wob, n4_w);
    fill_bias_rep<<<256, 256>>>(bq, bk, bv, bo);

    dim3 ggrid(DMODEL / GBN, MTOT / GBM);   // (8, 64)
    gemm_bf16<<<ggrid, 256, GEMM_SMEM>>>(xb, wqb, 0, 0);
    gemm_bf16<<<ggrid, 256, GEMM_SMEM>>>(kb, wkb, 1, 1);
    gemm_bf16<<<ggrid, 256, GEMM_SMEM>>>(vb, wvb, 2, 2);

    dim3 agrid(SEQ / QT, BATCH * NHEADS);   // (16, 64)
    attn_kernel<<<agrid, 256, ATTN_SMEM>>>();

    gemm_bf16<<<ggrid, 256, GEMM_SMEM>>>(ctxb, wob, 3, 3);

    ln_kernel<<<MTOT, 256>>>(query, gamma, beta, out);
}

// round 10
// speedup vs baseline: 4.3489x; 1.5379x over previous
#include <cuda_runtime.h>
#include <cuda_bf16.h>
#include <mma.h>
#include <cstdint>

using namespace nvcuda;

#define BATCH 4
#define SEQ 2048
#define DMODEL 1024
#define NHEADS 16
#define DK 64
#define MTOT (BATCH * SEQ)   // 8192

// ---------------- scratch ----------------------------------------------------
__device__ __nv_bfloat16 g_xb[MTOT * DMODEL];
__device__ __nv_bfloat16 g_kb[MTOT * DMODEL];
__device__ __nv_bfloat16 g_vb[MTOT * DMODEL];
__device__ __nv_bfloat16 g_Wqb[DMODEL * DMODEL];
__device__ __nv_bfloat16 g_Wkb[DMODEL * DMODEL];
__device__ __nv_bfloat16 g_Wvb[DMODEL * DMODEL];
__device__ __nv_bfloat16 g_Wob[DMODEL * DMODEL];
__device__ __nv_bfloat16 g_Qb[BATCH * NHEADS * SEQ * DK];   // [B,H,S,DK]
__device__ __nv_bfloat16 g_Kb[BATCH * NHEADS * SEQ * DK];
__device__ __nv_bfloat16 g_Vb[BATCH * NHEADS * SEQ * DK];
__device__ __nv_bfloat16 g_ctxb[MTOT * DMODEL];
__device__ float g_proj[MTOT * DMODEL];
__device__ float g_bias_rep[4 * 16 * DMODEL];

// ---------------- converts ----------------------------------------------------
__global__ void __launch_bounds__(256)
f2b_kernel(const float* __restrict__ src, __nv_bfloat16* __restrict__ dst, int n4) {
    int i = blockIdx.x * blockDim.x + threadIdx.x;
    if (i >= n4) return;
    float4 v = ((const float4*)src)[i];
    ((__nv_bfloat162*)dst)[2 * i]     = __float22bfloat162_rn(make_float2(v.x, v.y));
    ((__nv_bfloat162*)dst)[2 * i + 1] = __float22bfloat162_rn(make_float2(v.z, v.w));
}

__global__ void fill_bias_rep(const float* __restrict__ bq, const float* __restrict__ bk,
                              const float* __restrict__ bv, const float* __restrict__ bo) {
    int idx = blockIdx.x * blockDim.x + threadIdx.x;
    if (idx >= 4 * 16 * DMODEL) return;
    int which = idx >> 14;
    int n = idx & (DMODEL - 1);
    const float* src = (which == 0) ? bq : (which == 1) ? bk : (which == 2) ? bv : bo;
    g_bias_rep[idx] = src[n];
}

// ---------------- PTX helpers -------------------------------------------------
__device__ __forceinline__ void cp_async16(void* smem_dst, const void* gmem_src) {
    unsigned int a = (unsigned int)__cvta_generic_to_shared(smem_dst);
    asm volatile("cp.async.cg.shared.global [%0], [%1], 16;\n" :: "r"(a), "l"(gmem_src));
}
#define CP_COMMIT() asm volatile("cp.async.commit_group;\n" ::: "memory")
#define CP_WAIT0()  asm volatile("cp.async.wait_group 0;\n" ::: "memory")

__device__ __forceinline__ unsigned int s2u(const void* p) {
    return (unsigned int)__cvta_generic_to_shared(p);
}
__device__ __forceinline__ void ldmx4(uint32_t& r0, uint32_t& r1, uint32_t& r2, uint32_t& r3,
                                      unsigned int a) {
    asm volatile("ldmatrix.sync.aligned.m8n8.x4.shared.b16 {%0,%1,%2,%3},[%4];"
                 : "=r"(r0), "=r"(r1), "=r"(r2), "=r"(r3) : "r"(a));
}
__device__ __forceinline__ void ldmx2(uint32_t& r0, uint32_t& r1, unsigned int a) {
    asm volatile("ldmatrix.sync.aligned.m8n8.x2.shared.b16 {%0,%1},[%2];"
                 : "=r"(r0), "=r"(r1) : "r"(a));
}
__device__ __forceinline__ void ldmx2t(uint32_t& r0, uint32_t& r1, unsigned int a) {
    asm volatile("ldmatrix.sync.aligned.m8n8.x2.trans.shared.b16 {%0,%1},[%2];"
                 : "=r"(r0), "=r"(r1) : "r"(a));
}
__device__ __forceinline__ void mma16816(float& d0, float& d1, float& d2, float& d3,
                                         uint32_t a0, uint32_t a1, uint32_t a2, uint32_t a3,
                                         uint32_t b0, uint32_t b1) {
    asm volatile(
        "mma.sync.aligned.m16n8k16.row.col.f32.bf16.bf16.f32 "
        "{%0,%1,%2,%3}, {%4,%5,%6,%7}, {%8,%9}, {%0,%1,%2,%3};"
        : "+f"(d0), "+f"(d1), "+f"(d2), "+f"(d3)
        : "r"(a0), "r"(a1), "r"(a2), "r"(a3), "r"(b0), "r"(b1));
}
__device__ __forceinline__ float fexp2(float x) {
    float y;
    asm("ex2.approx.ftz.f32 %0, %1;" : "=f"(y) : "f"(x));
    return y;
}
__device__ __forceinline__ uint32_t packbf(float a, float b) {
    __nv_bfloat162 t = __float22bfloat162_rn(make_float2(a, b));
    return *reinterpret_cast<uint32_t*>(&t);
}

// ---------------- bf16 GEMM with 2-stage cp.async pipeline --------------------
#define GBM 128
#define GBN 128
#define GBK 64
#define GLDA 72
#define GLDB 136
#define GEMM_SMEM (2 * (GBM * GLDA + GBK * GLDB) * 2)   // 71680 B
#define NKT (DMODEL / GBK)                              // 16

__global__ void __launch_bounds__(256, 2)
gemm_bf16(const __nv_bfloat16* __restrict__ A, const __nv_bfloat16* __restrict__ W,
          int bias_idx, int out_sel) {
    extern __shared__ __align__(16) char smraw[];
    __nv_bfloat16* As[2] = { (__nv_bfloat16*)smraw,
                             (__nv_bfloat16*)smraw + GBM * GLDA };
    __nv_bfloat16* Bs[2] = { (__nv_bfloat16*)smraw + 2 * GBM * GLDA,
                             (__nv_bfloat16*)smraw + 2 * GBM * GLDA + GBK * GLDB };

    const int t = threadIdx.x;
    const int warp = t >> 5;
    const int wm = warp >> 1;
    const int wn = warp & 1;
    const int row0 = blockIdx.y * GBM;
    const int col0 = blockIdx.x * GBN;
    const float* brep = g_bias_rep + bias_idx * 16 * DMODEL;

    wmma::fragment<wmma::accumulator, 16, 16, 16, float> c[2][4];
#pragma unroll
    for (int i = 0; i < 2; i++)
#pragma unroll
        for (int j = 0; j < 4; j++)
            wmma::load_matrix_sync(c[i][j], brep + col0 + wn * 64 + j * 16, DMODEL,
                                   wmma::mem_row_major);

    {
#pragma unroll
        for (int i = 0; i < 4; i++) {
            int idx = t + i * 256;
            int r = idx >> 3, v = idx & 7;
            cp_async16(As[0] + r * GLDA + v * 8, A + (size_t)(row0 + r) * DMODEL + v * 8);
        }
#pragma unroll
        for (int i = 0; i < 4; i++) {
            int idx = t + i * 256;
            int r = idx >> 4, v = idx & 15;
            cp_async16(Bs[0] + r * GLDB + v * 8, W + (size_t)r * DMODEL + col0 + v * 8);
        }
        CP_COMMIT();
    }

    for (int kt = 0; kt < NKT; kt++) {
        const int buf = kt & 1;
        CP_WAIT0();
        __syncthreads();
        if (kt + 1 < NKT) {
            const int k1 = (kt + 1) * GBK;
#pragma unroll
            for (int i = 0; i < 4; i++) {
                int idx = t + i * 256;
                int r = idx >> 3, v = idx & 7;
                cp_async16(As[buf ^ 1] + r * GLDA + v * 8,
                           A + (size_t)(row0 + r) * DMODEL + k1 + v * 8);
            }
#pragma unroll
            for (int i = 0; i < 4; i++) {
                int idx = t + i * 256;
                int r = idx >> 4, v = idx & 15;
                cp_async16(Bs[buf ^ 1] + r * GLDB + v * 8,
                           W + (size_t)(k1 + r) * DMODEL + col0 + v * 8);
            }
            CP_COMMIT();
        }

#pragma unroll
        for (int ks = 0; ks < GBK / 16; ks++) {
            wmma::fragment<wmma::matrix_a, 16, 16, 16, __nv_bfloat16, wmma::row_major> a[2];
            wmma::fragment<wmma::matrix_b, 16, 16, 16, __nv_bfloat16, wmma::row_major> b[4];
#pragma unroll
            for (int i = 0; i < 2; i++)
                wmma::load_matrix_sync(a[i], As[buf] + (wm * 32 + i * 16) * GLDA + ks * 16, GLDA);
#pragma unroll
            for (int j = 0; j < 4; j++)
                wmma::load_matrix_sync(b[j], Bs[buf] + ks * 16 * GLDB + wn * 64 + j * 16, GLDB);
#pragma unroll
            for (int i = 0; i < 2; i++)
#pragma unroll
                for (int j = 0; j < 4; j++)
                    wmma::mma_sync(c[i][j], a[i], b[j], c[i][j]);
        }
        __syncthreads();
    }

    if (out_sel <= 2) {
        __nv_bfloat16* outb = (out_sel == 0) ? g_Qb : (out_sel == 1) ? g_Kb : g_Vb;
        float* stage = (float*)smraw;
#pragma unroll
        for (int i = 0; i < 2; i++)
#pragma unroll
            for (int j = 0; j < 4; j++)
                wmma::store_matrix_sync(stage + (wm * 32 + i * 16) * 132 + wn * 64 + j * 16,
                                        c[i][j], 132, wmma::mem_row_major);
        __syncthreads();
        const int r = t >> 1, hf = t & 1;
        const int gr = row0 + r;
        const int gc = col0 + hf * 64;
        const int b = gr >> 11, s0 = gr & (SEQ - 1), h = gc >> 6;
        __nv_bfloat16* dst = outb + ((size_t)(b * NHEADS + h) * SEQ + s0) * DK;
        const float* src = stage + r * 132 + hf * 64;
#pragma unroll
        for (int v = 0; v < 32; v++)
            *(__nv_bfloat162*)(dst + 2 * v) =
                __float22bfloat162_rn(make_float2(src[2 * v], src[2 * v + 1]));
    } else {
#pragma unroll
        for (int i = 0; i < 2; i++) {
            int r0 = row0 + wm * 32 + i * 16;
#pragma unroll
            for (int j = 0; j < 4; j++)
                wmma::store_matrix_sync(g_proj + (size_t)r0 * DMODEL + col0 + wn * 64 + j * 16,
                                        c[i][j], DMODEL, wmma::mem_row_major);
        }
    }
}

// ---------------- Flash attention v2: register softmax + register O -----------
// CTA: 64 q-rows, 4 warps (128 thr). Warp w owns rows w*16..+16. KT=64, dk=64.
#define AQT 64
#define AKT 64
#define AALD 72   // bf16 leading dim (144 B rows)

__global__ void __launch_bounds__(128)
attn_kernel() {
    __shared__ __align__(16) __nv_bfloat16 Qs[AQT * AALD];
    __shared__ __align__(16) __nv_bfloat16 Ks[2][AKT * AALD];
    __shared__ __align__(16) __nv_bfloat16 Vs[2][AKT * AALD];

    const int t = threadIdx.x;
    const int lane = t & 31;
    const int warp = t >> 5;
    const int q0 = blockIdx.x * AQT;
    const int bh = blockIdx.y;
    const __nv_bfloat16* Qg = g_Qb + (size_t)bh * SEQ * DK;
    const __nv_bfloat16* Kg = g_Kb + (size_t)bh * SEQ * DK;
    const __nv_bfloat16* Vg = g_Vb + (size_t)bh * SEQ * DK;

    // prefetch K/V tile 0 (1024 x 16B chunks, 8/thread)
#pragma unroll
    for (int i = 0; i < 4; i++) {
        int idx = t + i * 128;
        int r = idx >> 3, v = idx & 7;
        cp_async16(&Ks[0][r * AALD + v * 8], Kg + (size_t)r * DK + v * 8);
        cp_async16(&Vs[0][r * AALD + v * 8], Vg + (size_t)r * DK + v * 8);
    }
    CP_COMMIT();

    // stage Q (512 chunks, 4/thread)
#pragma unroll
    for (int i = 0; i < 4; i++) {
        int idx = t + i * 128;
        int r = idx >> 3, v = idx & 7;
        *(uint4*)(Qs + r * AALD + v * 8) = *(const uint4*)(Qg + (size_t)(q0 + r) * DK + v * 8);
    }
    __syncthreads();

    // Q A-fragments
    uint32_t qa[4][4];
    {
        int row = warp * 16 + (lane & 15);
        int col8 = (lane >> 4) << 3;
#pragma unroll
        for (int ks = 0; ks < 4; ks++)
            ldmx4(qa[ks][0], qa[ks][1], qa[ks][2], qa[ks][3],
                  s2u(Qs + row * AALD + ks * 16 + col8));
    }

    float ofr[8][4];
#pragma unroll
    for (int f = 0; f < 8; f++)
#pragma unroll
        for (int e = 0; e < 4; e++) ofr[f][e] = 0.f;
    float mt0 = -1e30f, mt1 = -1e30f, l0 = 0.f, l1 = 0.f;

    const float CS = 0.125f * 1.4426950408889634f;   // scale * log2(e)

    const int NTILE = SEQ / AKT;   // 32
    for (int kt = 0; kt < NTILE; kt++) {
        const int buf = kt & 1;
        CP_WAIT0();
        __syncthreads();
        if (kt + 1 < NTILE) {
            const __nv_bfloat16* Kn = Kg + (size_t)(kt + 1) * AKT * DK;
            const __nv_bfloat16* Vn = Vg + (size_t)(kt + 1) * AKT * DK;
#pragma unroll
            for (int i = 0; i < 4; i++) {
                int idx = t + i * 128;
                int r = idx >> 3, v = idx & 7;
                cp_async16(&Ks[buf ^ 1][r * AALD + v * 8], Kn + (size_t)r * DK + v * 8);
                cp_async16(&Vs[buf ^ 1][r * AALD + v * 8], Vn + (size_t)r * DK + v * 8);
            }
            CP_COMMIT();
        }

        // ---- S = Q @ K^T ----
        float sfr[8][4];
#pragma unroll
        for (int f = 0; f < 8; f++)
#pragma unroll
            for (int e = 0; e < 4; e++) sfr[f][e] = 0.f;

        {
            int krow = (lane & 7);
            int kc8 = ((lane >> 3) & 1) << 3;
#pragma unroll
            for (int ks = 0; ks < 4; ks++) {
#pragma unroll
                for (int f = 0; f < 8; f++) {
                    uint32_t b0, b1;
                    ldmx2(b0, b1, s2u(&Ks[buf][(f * 8 + krow) * AALD + ks * 16 + kc8]));
                    mma16816(sfr[f][0], sfr[f][1], sfr[f][2], sfr[f][3],
                             qa[ks][0], qa[ks][1], qa[ks][2], qa[ks][3], b0, b1);
                }
            }
        }

        // ---- register softmax ----
        float mx0 = -1e30f, mx1 = -1e30f;
#pragma unroll
        for (int f = 0; f < 8; f++) {
            sfr[f][0] *= CS; sfr[f][1] *= CS; sfr[f][2] *= CS; sfr[f][3] *= CS;
            mx0 = fmaxf(mx0, fmaxf(sfr[f][0], sfr[f][1]));
            mx1 = fmaxf(mx1, fmaxf(sfr[f][2], sfr[f][3]));
        }
        mx0 = fmaxf(mx0, __shfl_xor_sync(0xffffffffu, mx0, 1));
        mx0 = fmaxf(mx0, __shfl_xor_sync(0xffffffffu, mx0, 2));
        mx1 = fmaxf(mx1, __shfl_xor_sync(0xffffffffu, mx1, 1));
        mx1 = fmaxf(mx1, __shfl_xor_sync(0xffffffffu, mx1, 2));
        float m0n = fmaxf(mt0, mx0), m1n = fmaxf(mt1, mx1);
        float al0 = fexp2(mt0 - m0n), al1 = fexp2(mt1 - m1n);
        mt0 = m0n; mt1 = m1n;

        float ps0 = 0.f, ps1 = 0.f;
#pragma unroll
        for (int f = 0; f < 8; f++) {
            sfr[f][0] = fexp2(sfr[f][0] - m0n);
            sfr[f][1] = fexp2(sfr[f][1] - m0n);
            sfr[f][2] = fexp2(sfr[f][2] - m1n);
            sfr[f][3] = fexp2(sfr[f][3] - m1n);
            ps0 += sfr[f][0] + sfr[f][1];
            ps1 += sfr[f][2] + sfr[f][3];
        }
        l0 = l0 * al0 + ps0;
        l1 = l1 * al1 + ps1;

#pragma unroll
        for (int f = 0; f < 8; f++) {
            ofr[f][0] *= al0; ofr[f][1] *= al0;
            ofr[f][2] *= al1; ofr[f][3] *= al1;
        }

        // ---- O += P @ V ----
        {
            int vrow = (lane & 15);
#pragma unroll
            for (int ks = 0; ks < 4; ks++) {
                uint32_t a0 = packbf(sfr[2 * ks][0],     sfr[2 * ks][1]);
                uint32_t a1 = packbf(sfr[2 * ks][2],     sfr[2 * ks][3]);
                uint32_t a2 = packbf(sfr[2 * ks + 1][0], sfr[2 * ks + 1][1]);
                uint32_t a3 = packbf(sfr[2 * ks + 1][2], sfr[2 * ks + 1][3]);
#pragma unroll
                for (int f = 0; f < 8; f++) {
                    uint32_t b0, b1;
                    ldmx2t(b0, b1, s2u(&Vs[buf][(ks * 16 + vrow) * AALD + f * 8]));
                    mma16816(ofr[f][0], ofr[f][1], ofr[f][2], ofr[f][3],
                             a0, a1, a2, a3, b0, b1);
                }
            }
        }
    }

    // final l reduction across quad
    l0 += __shfl_xor_sync(0xffffffffu, l0, 1);
    l0 += __shfl_xor_sync(0xffffffffu, l0, 2);
    l1 += __shfl_xor_sync(0xffffffffu, l1, 1);
    l1 += __shfl_xor_sync(0xffffffffu, l1, 2);
    float inv0 = 1.f / l0, inv1 = 1.f / l1;

    // epilogue
    const int b = bh >> 4, h = bh & 15;
    int row0 = q0 + warp * 16 + (lane >> 2);
    int colb = h * DK + 2 * (lane & 3);
#pragma unroll
    for (int f = 0; f < 8; f++) {
        *(__nv_bfloat162*)(g_ctxb + (size_t)(b * SEQ + row0) * DMODEL + colb + f * 8) =
            __float22bfloat162_rn(make_float2(ofr[f][0] * inv0, ofr[f][1] * inv0));
        *(__nv_bfloat162*)(g_ctxb + (size_t)(b * SEQ + row0 + 8) * DMODEL + colb + f * 8) =
            __float22bfloat162_rn(make_float2(ofr[f][2] * inv1, ofr[f][3] * inv1));
    }
}

// ---------------- residual + LayerNorm ---------------------------------------
__global__ void __launch_bounds__(256)
ln_kernel(const float* __restrict__ residual, const float* __restrict__ gamma,
          const float* __restrict__ beta, float* __restrict__ out) {
    const int row = blockIdx.x;
    const int t = threadIdx.x;
    const size_t base = (size_t)row * DMODEL + t * 4;

    float4 r4 = *(const float4*)(residual + base);
    float4 p4 = *(const float4*)(g_proj + base);
    float x0 = r4.x + p4.x, x1 = r4.y + p4.y, x2 = r4.z + p4.z, x3 = r4.w + p4.w;

    float s = x0 + x1 + x2 + x3;
    float ss = x0 * x0 + x1 * x1 + x2 * x2 + x3 * x3;
#pragma unroll
    for (int off = 16; off > 0; off >>= 1) {
        s += __shfl_xor_sync(0xffffffffu, s, off);
        ss += __shfl_xor_sync(0xffffffffu, ss, off);
    }
    __shared__ float rs[8], rss[8], stat[2];
    int w = t >> 5, lane = t & 31;
    if (lane == 0) { rs[w] = s; rss[w] = ss; }
    __syncthreads();
    if (t == 0) {
        float S = 0.f, SS = 0.f;
#pragma unroll
        for (int i = 0; i < 8; i++) { S += rs[i]; SS += rss[i]; }
        float mean = S * (1.f / DMODEL);
        float var = SS * (1.f / DMODEL) - mean * mean;
        stat[0] = mean;
        stat[1] = rsqrtf(var + 1e-5f);
    }
    __syncthreads();
    float mean = stat[0], inv = stat[1];

    float4 g4 = *(const float4*)(gamma + t * 4);
    float4 b4 = *(const float4*)(beta + t * 4);
    float4 y;
    y.x = (x0 - mean) * inv * g4.x + b4.x;
    y.y = (x1 - mean) * inv * g4.y + b4.y;
    y.z = (x2 - mean) * inv * g4.z + b4.z;
    y.w = (x3 - mean) * inv * g4.w + b4.w;
    *(float4*)(out + base) = y;
}

// ---------------- launch ------------------------------------------------------
extern "C" void kernel_launch(void* const* d_in, const int* in_sizes, int n_in,
                              void* d_out, int out_size) {
    const float* query = (const float*)d_in[0];
    const float* key   = (const float*)d_in[1];
    const float* value = (const float*)d_in[2];
    const float* Wq    = (const float*)d_in[3];
    const float* bq    = (const float*)d_in[4];
    const float* Wk    = (const float*)d_in[5];
    const float* bk    = (const float*)d_in[6];
    const float* Wv    = (const float*)d_in[7];
    const float* bv    = (const float*)d_in[8];
    const float* Wo    = (const float*)d_in[9];
    const float* bo    = (const float*)d_in[10];
    const float* gamma = (const float*)d_in[11];
    const float* beta  = (const float*)d_in[12];
    float* out = (float*)d_out;

    static bool attr_done = false;
    if (!attr_done) {
        (void)cudaFuncSetAttribute(gemm_bf16,
                                   cudaFuncAttributeMaxDynamicSharedMemorySize, GEMM_SMEM);
        attr_done = true;
    }

    static __nv_bfloat16 *xb = nullptr, *kb, *vb, *wqb, *wkb, *wvb, *wob, *ctxb;
    if (!xb) {
        cudaGetSymbolAddress((void**)&xb,   g_xb);
        cudaGetSymbolAddress((void**)&kb,   g_kb);
        cudaGetSymbolAddress((void**)&vb,   g_vb);
        cudaGetSymbolAddress((void**)&wqb,  g_Wqb);
        cudaGetSymbolAddress((void**)&wkb,  g_Wkb);
        cudaGetSymbolAddress((void**)&wvb,  g_Wvb);
        cudaGetSymbolAddress((void**)&wob,  g_Wob);
        cudaGetSymbolAddress((void**)&ctxb, g_ctxb);
    }

    const int n4_act = MTOT * DMODEL / 4;
    const int n4_w   = DMODEL * DMODEL / 4;
    f2b_kernel<<<n4_act / 256, 256>>>(query, xb, n4_act);
    f2b_kernel<<<n4_act / 256, 256>>>(key,   kb, n4_act);
    f2b_kernel<<<n4_act / 256, 256>>>(value, vb, n4_act);
    f2b_kernel<<<n4_w / 256, 256>>>(Wq, wqb, n4_w);
    f2b_kernel<<<n4_w / 256, 256>>>(Wk, wkb, n4_w);
    f2b_kernel<<<n4_w / 256, 256>>>(Wv, wvb, n4_w);
    f2b_kernel<<<n4_w / 256, 256>>>(Wo, wob, n4_w);
    fill_bias_rep<<<256, 256>>>(bq, bk, bv, bo);

    dim3 ggrid(DMODEL / GBN, MTOT / GBM);   // (8, 64)
    gemm_bf16<<<ggrid, 256, GEMM_SMEM>>>(xb, wqb, 0, 0);
    gemm_bf16<<<ggrid, 256, GEMM_SMEM>>>(kb, wkb, 1, 1);
    gemm_bf16<<<ggrid, 256, GEMM_SMEM>>>(vb, wvb, 2, 2);

    dim3 agrid(SEQ / AQT, BATCH * NHEADS);  // (32, 64)
    attn_kernel<<<agrid, 128>>>();

    gemm_bf16<<<ggrid, 256, GEMM_SMEM>>>(ctxb, wob, 3, 3);

    ln_kernel<<<MTOT, 256>>>(query, gamma, beta, out);
}

// round 11
// speedup vs baseline: 4.3644x; 1.0036x over previous
#include <cuda_runtime.h>
#include <cuda_bf16.h>
#include <mma.h>
#include <cstdint>

using namespace nvcuda;

#define BATCH 4
#define SEQ 2048
#define DMODEL 1024
#define NHEADS 16
#define DK 64
#define MTOT (BATCH * SEQ)   // 8192

// ---------------- scratch ----------------------------------------------------
__device__ __nv_bfloat16 g_xb[MTOT * DMODEL];
__device__ __nv_bfloat16 g_kb[MTOT * DMODEL];
__device__ __nv_bfloat16 g_vb[MTOT * DMODEL];
__device__ __nv_bfloat16 g_Wqb[DMODEL * DMODEL];
__device__ __nv_bfloat16 g_Wkb[DMODEL * DMODEL];
__device__ __nv_bfloat16 g_Wvb[DMODEL * DMODEL];
__device__ __nv_bfloat16 g_Wob[DMODEL * DMODEL];
__device__ __nv_bfloat16 g_Qb[BATCH * NHEADS * SEQ * DK];   // [B,H,S,DK]
__device__ __nv_bfloat16 g_Kb[BATCH * NHEADS * SEQ * DK];
__device__ __nv_bfloat16 g_Vb[BATCH * NHEADS * SEQ * DK];
__device__ __nv_bfloat16 g_ctxb[MTOT * DMODEL];
__device__ float g_proj[MTOT * DMODEL];
__device__ float g_bias_rep[4 * 16 * DMODEL];

// ---------------- converts ----------------------------------------------------
__global__ void __launch_bounds__(256)
f2b_kernel(const float* __restrict__ src, __nv_bfloat16* __restrict__ dst, int n4) {
    int i = blockIdx.x * blockDim.x + threadIdx.x;
    if (i >= n4) return;
    float4 v = ((const float4*)src)[i];
    ((__nv_bfloat162*)dst)[2 * i]     = __float22bfloat162_rn(make_float2(v.x, v.y));
    ((__nv_bfloat162*)dst)[2 * i + 1] = __float22bfloat162_rn(make_float2(v.z, v.w));
}

__global__ void fill_bias_rep(const float* __restrict__ bq, const float* __restrict__ bk,
                              const float* __restrict__ bv, const float* __restrict__ bo) {
    int idx = blockIdx.x * blockDim.x + threadIdx.x;
    if (idx >= 4 * 16 * DMODEL) return;
    int which = idx >> 14;
    int n = idx & (DMODEL - 1);
    const float* src = (which == 0) ? bq : (which == 1) ? bk : (which == 2) ? bv : bo;
    g_bias_rep[idx] = src[n];
}

// ---------------- PTX helpers -------------------------------------------------
__device__ __forceinline__ void cp_async16(void* smem_dst, const void* gmem_src) {
    unsigned int a = (unsigned int)__cvta_generic_to_shared(smem_dst);
    asm volatile("cp.async.cg.shared.global [%0], [%1], 16;\n" :: "r"(a), "l"(gmem_src));
}
#define CP_COMMIT() asm volatile("cp.async.commit_group;\n" ::: "memory")
#define CP_WAIT0()  asm volatile("cp.async.wait_group 0;\n" ::: "memory")

__device__ __forceinline__ unsigned int s2u(const void* p) {
    return (unsigned int)__cvta_generic_to_shared(p);
}
__device__ __forceinline__ void ldmx4(uint32_t& r0, uint32_t& r1, uint32_t& r2, uint32_t& r3,
                                      unsigned int a) {
    asm volatile("ldmatrix.sync.aligned.m8n8.x4.shared.b16 {%0,%1,%2,%3},[%4];"
                 : "=r"(r0), "=r"(r1), "=r"(r2), "=r"(r3) : "r"(a));
}
__device__ __forceinline__ void ldmx4t(uint32_t& r0, uint32_t& r1, uint32_t& r2, uint32_t& r3,
                                       unsigned int a) {
    asm volatile("ldmatrix.sync.aligned.m8n8.x4.trans.shared.b16 {%0,%1,%2,%3},[%4];"
                 : "=r"(r0), "=r"(r1), "=r"(r2), "=r"(r3) : "r"(a));
}
__device__ __forceinline__ void mma16816(float& d0, float& d1, float& d2, float& d3,
                                         uint32_t a0, uint32_t a1, uint32_t a2, uint32_t a3,
                                         uint32_t b0, uint32_t b1) {
    asm volatile(
        "mma.sync.aligned.m16n8k16.row.col.f32.bf16.bf16.f32 "
        "{%0,%1,%2,%3}, {%4,%5,%6,%7}, {%8,%9}, {%0,%1,%2,%3};"
        : "+f"(d0), "+f"(d1), "+f"(d2), "+f"(d3)
        : "r"(a0), "r"(a1), "r"(a2), "r"(a3), "r"(b0), "r"(b1));
}
__device__ __forceinline__ float fexp2(float x) {
    float y;
    asm("ex2.approx.ftz.f32 %0, %1;" : "=f"(y) : "f"(x));
    return y;
}
__device__ __forceinline__ uint32_t packbf(float a, float b) {
    __nv_bfloat162 t = __float22bfloat162_rn(make_float2(a, b));
    return *reinterpret_cast<uint32_t*>(&t);
}

// ---------------- bf16 GEMM with 2-stage cp.async pipeline --------------------
#define GBM 128
#define GBN 128
#define GBK 64
#define GLDA 72
#define GLDB 136
#define GEMM_SMEM (2 * (GBM * GLDA + GBK * GLDB) * 2)   // 71680 B
#define NKT (DMODEL / GBK)                              // 16

__global__ void __launch_bounds__(256, 2)
gemm_bf16(const __nv_bfloat16* __restrict__ A, const __nv_bfloat16* __restrict__ W,
          int bias_idx, int out_sel) {
    extern __shared__ __align__(16) char smraw[];
    __nv_bfloat16* As[2] = { (__nv_bfloat16*)smraw,
                             (__nv_bfloat16*)smraw + GBM * GLDA };
    __nv_bfloat16* Bs[2] = { (__nv_bfloat16*)smraw + 2 * GBM * GLDA,
                             (__nv_bfloat16*)smraw + 2 * GBM * GLDA + GBK * GLDB };

    const int t = threadIdx.x;
    const int warp = t >> 5;
    const int wm = warp >> 1;
    const int wn = warp & 1;
    const int row0 = blockIdx.y * GBM;
    const int col0 = blockIdx.x * GBN;
    const float* brep = g_bias_rep + bias_idx * 16 * DMODEL;

    wmma::fragment<wmma::accumulator, 16, 16, 16, float> c[2][4];
#pragma unroll
    for (int i = 0; i < 2; i++)
#pragma unroll
        for (int j = 0; j < 4; j++)
            wmma::load_matrix_sync(c[i][j], brep + col0 + wn * 64 + j * 16, DMODEL,
                                   wmma::mem_row_major);

    {
#pragma unroll
        for (int i = 0; i < 4; i++) {
            int idx = t + i * 256;
            int r = idx >> 3, v = idx & 7;
            cp_async16(As[0] + r * GLDA + v * 8, A + (size_t)(row0 + r) * DMODEL + v * 8);
        }
#pragma unroll
        for (int i = 0; i < 4; i++) {
            int idx = t + i * 256;
            int r = idx >> 4, v = idx & 15;
            cp_async16(Bs[0] + r * GLDB + v * 8, W + (size_t)r * DMODEL + col0 + v * 8);
        }
        CP_COMMIT();
    }

    for (int kt = 0; kt < NKT; kt++) {
        const int buf = kt & 1;
        CP_WAIT0();
        __syncthreads();
        if (kt + 1 < NKT) {
            const int k1 = (kt + 1) * GBK;
#pragma unroll
            for (int i = 0; i < 4; i++) {
                int idx = t + i * 256;
                int r = idx >> 3, v = idx & 7;
                cp_async16(As[buf ^ 1] + r * GLDA + v * 8,
                           A + (size_t)(row0 + r) * DMODEL + k1 + v * 8);
            }
#pragma unroll
            for (int i = 0; i < 4; i++) {
                int idx = t + i * 256;
                int r = idx >> 4, v = idx & 15;
                cp_async16(Bs[buf ^ 1] + r * GLDB + v * 8,
                           W + (size_t)(k1 + r) * DMODEL + col0 + v * 8);
            }
            CP_COMMIT();
        }

#pragma unroll
        for (int ks = 0; ks < GBK / 16; ks++) {
            wmma::fragment<wmma::matrix_a, 16, 16, 16, __nv_bfloat16, wmma::row_major> a[2];
            wmma::fragment<wmma::matrix_b, 16, 16, 16, __nv_bfloat16, wmma::row_major> b[4];
#pragma unroll
            for (int i = 0; i < 2; i++)
                wmma::load_matrix_sync(a[i], As[buf] + (wm * 32 + i * 16) * GLDA + ks * 16, GLDA);
#pragma unroll
            for (int j = 0; j < 4; j++)
                wmma::load_matrix_sync(b[j], Bs[buf] + ks * 16 * GLDB + wn * 64 + j * 16, GLDB);
#pragma unroll
            for (int i = 0; i < 2; i++)
#pragma unroll
                for (int j = 0; j < 4; j++)
                    wmma::mma_sync(c[i][j], a[i], b[j], c[i][j]);
        }
        __syncthreads();
    }

    if (out_sel <= 2) {
        __nv_bfloat16* outb = (out_sel == 0) ? g_Qb : (out_sel == 1) ? g_Kb : g_Vb;
        float* stage = (float*)smraw;
#pragma unroll
        for (int i = 0; i < 2; i++)
#pragma unroll
            for (int j = 0; j < 4; j++)
                wmma::store_matrix_sync(stage + (wm * 32 + i * 16) * 132 + wn * 64 + j * 16,
                                        c[i][j], 132, wmma::mem_row_major);
        __syncthreads();
        const int r = t >> 1, hf = t & 1;
        const int gr = row0 + r;
        const int gc = col0 + hf * 64;
        const int b = gr >> 11, s0 = gr & (SEQ - 1), h = gc >> 6;
        __nv_bfloat16* dst = outb + ((size_t)(b * NHEADS + h) * SEQ + s0) * DK;
        const float* src = stage + r * 132 + hf * 64;
#pragma unroll
        for (int v = 0; v < 32; v++)
            *(__nv_bfloat162*)(dst + 2 * v) =
                __float22bfloat162_rn(make_float2(src[2 * v], src[2 * v + 1]));
    } else {
#pragma unroll
        for (int i = 0; i < 2; i++) {
            int r0 = row0 + wm * 32 + i * 16;
#pragma unroll
            for (int j = 0; j < 4; j++)
                wmma::store_matrix_sync(g_proj + (size_t)r0 * DMODEL + col0 + wn * 64 + j * 16,
                                        c[i][j], DMODEL, wmma::mem_row_major);
        }
    }
}

// ---------------- Flash attention v3: QT=128, 8 warps, ldmatrix.x4 ------------
// Warp w owns q-rows w*16..+16. KT=64, dk=64. Register softmax + register O.
#define AQT 128
#define AKT 64
#define AALD 72   // bf16 leading dim (144 B rows)
#define ATTN_SMEM ((AQT * AALD + 4 * AKT * AALD) * 2)   // 55296 B

__global__ void __launch_bounds__(256, 2)
attn_kernel() {
    extern __shared__ __align__(16) char smraw[];
    __nv_bfloat16* Qs = (__nv_bfloat16*)smraw;                      // 128 x 72
    __nv_bfloat16* Ks0 = Qs + AQT * AALD;                           // 2 x 64 x 72
    __nv_bfloat16* Vs0 = Ks0 + 2 * AKT * AALD;
    __nv_bfloat16* Ksb[2] = { Ks0, Ks0 + AKT * AALD };
    __nv_bfloat16* Vsb[2] = { Vs0, Vs0 + AKT * AALD };

    const int t = threadIdx.x;
    const int lane = t & 31;
    const int warp = t >> 5;          // 0..7
    const int q0 = blockIdx.x * AQT;
    const int bh = blockIdx.y;
    const __nv_bfloat16* Qg = g_Qb + (size_t)bh * SEQ * DK;
    const __nv_bfloat16* Kg = g_Kb + (size_t)bh * SEQ * DK;
    const __nv_bfloat16* Vg = g_Vb + (size_t)bh * SEQ * DK;

    // prefetch K/V tile 0: 512 + 512 chunks of 16B, 2+2 per thread
#pragma unroll
    for (int i = 0; i < 2; i++) {
        int idx = t + i * 256;
        int r = idx >> 3, v = idx & 7;
        cp_async16(Ksb[0] + r * AALD + v * 8, Kg + (size_t)r * DK + v * 8);
        cp_async16(Vsb[0] + r * AALD + v * 8, Vg + (size_t)r * DK + v * 8);
    }
    CP_COMMIT();

    // stage Q: 1024 chunks, 4/thread
#pragma unroll
    for (int i = 0; i < 4; i++) {
        int idx = t + i * 256;
        int r = idx >> 3, v = idx & 7;
        *(uint4*)(Qs + r * AALD + v * 8) = *(const uint4*)(Qg + (size_t)(q0 + r) * DK + v * 8);
    }
    __syncthreads();

    // Q A-fragments: qa[ks][0..3] (rows warp*16..+16, k = ks*16..+16)
    uint32_t qa[4][4];
    {
        int row = warp * 16 + (lane & 15);
        int col8 = (lane >> 4) << 3;
#pragma unroll
        for (int ks = 0; ks < 4; ks++)
            ldmx4(qa[ks][0], qa[ks][1], qa[ks][2], qa[ks][3],
                  s2u(Qs + row * AALD + ks * 16 + col8));
    }

    float ofr[8][4];
#pragma unroll
    for (int f = 0; f < 8; f++)
#pragma unroll
        for (int e = 0; e < 4; e++) ofr[f][e] = 0.f;
    float mt0 = -1e30f, mt1 = -1e30f, l0 = 0.f, l1 = 0.f;

    const float CS = 0.125f * 1.4426950408889634f;   // scale * log2(e)

    const int NTILE = SEQ / AKT;   // 32
    for (int kt = 0; kt < NTILE; kt++) {
        const int buf = kt & 1;
        CP_WAIT0();
        __syncthreads();
        if (kt + 1 < NTILE) {
            const __nv_bfloat16* Kn = Kg + (size_t)(kt + 1) * AKT * DK;
            const __nv_bfloat16* Vn = Vg + (size_t)(kt + 1) * AKT * DK;
#pragma unroll
            for (int i = 0; i < 2; i++) {
                int idx = t + i * 256;
                int r = idx >> 3, v = idx & 7;
                cp_async16(Ksb[buf ^ 1] + r * AALD + v * 8, Kn + (size_t)r * DK + v * 8);
                cp_async16(Vsb[buf ^ 1] + r * AALD + v * 8, Vn + (size_t)r * DK + v * 8);
            }
            CP_COMMIT();
        }

        // ---- S = Q @ K^T (16 x 64 per warp) ----
        float sfr[8][4];
#pragma unroll
        for (int f = 0; f < 8; f++)
#pragma unroll
            for (int e = 0; e < 4; e++) sfr[f][e] = 0.f;

        {
            const __nv_bfloat16* Kt = Ksb[buf];
            int krow = (lane & 15);
            int kc8 = (lane >> 4) << 3;
#pragma unroll
            for (int ks = 0; ks < 4; ks++) {
#pragma unroll
                for (int fb = 0; fb < 4; fb++) {   // 16-key blocks
                    uint32_t k0, k1, k2, k3;
                    // m0={n lo,k lo} m1={n hi,k lo} m2={n lo,k hi} m3={n hi,k hi}
                    ldmx4(k0, k1, k2, k3,
                          s2u(Kt + (fb * 16 + krow) * AALD + ks * 16 + kc8));
                    mma16816(sfr[2 * fb][0], sfr[2 * fb][1], sfr[2 * fb][2], sfr[2 * fb][3],
                             qa[ks][0], qa[ks][1], qa[ks][2], qa[ks][3], k0, k2);
                    mma16816(sfr[2 * fb + 1][0], sfr[2 * fb + 1][1], sfr[2 * fb + 1][2], sfr[2 * fb + 1][3],
                             qa[ks][0], qa[ks][1], qa[ks][2], qa[ks][3], k1, k3);
                }
            }
        }

        // ---- register softmax (rows lane>>2 and +8) ----
        float mx0 = -1e30f, mx1 = -1e30f;
#pragma unroll
        for (int f = 0; f < 8; f++) {
            sfr[f][0] *= CS; sfr[f][1] *= CS; sfr[f][2] *= CS; sfr[f][3] *= CS;
            mx0 = fmaxf(mx0, fmaxf(sfr[f][0], sfr[f][1]));
            mx1 = fmaxf(mx1, fmaxf(sfr[f][2], sfr[f][3]));
        }
        mx0 = fmaxf(mx0, __shfl_xor_sync(0xffffffffu, mx0, 1));
        mx0 = fmaxf(mx0, __shfl_xor_sync(0xffffffffu, mx0, 2));
        mx1 = fmaxf(mx1, __shfl_xor_sync(0xffffffffu, mx1, 1));
        mx1 = fmaxf(mx1, __shfl_xor_sync(0xffffffffu, mx1, 2));
        float m0n = fmaxf(mt0, mx0), m1n = fmaxf(mt1, mx1);
        float al0 = fexp2(mt0 - m0n), al1 = fexp2(mt1 - m1n);
        mt0 = m0n; mt1 = m1n;

        float ps0 = 0.f, ps1 = 0.f;
#pragma unroll
        for (int f = 0; f < 8; f++) {
            sfr[f][0] = fexp2(sfr[f][0] - m0n);
            sfr[f][1] = fexp2(sfr[f][1] - m0n);
            sfr[f][2] = fexp2(sfr[f][2] - m1n);
            sfr[f][3] = fexp2(sfr[f][3] - m1n);
            ps0 += sfr[f][0] + sfr[f][1];
            ps1 += sfr[f][2] + sfr[f][3];
        }
        l0 = l0 * al0 + ps0;
        l1 = l1 * al1 + ps1;

#pragma unroll
        for (int f = 0; f < 8; f++) {
            ofr[f][0] *= al0; ofr[f][1] *= al0;
            ofr[f][2] *= al1; ofr[f][3] *= al1;
        }

        // ---- O += P @ V ----
        {
            const __nv_bfloat16* Vt = Vsb[buf];
            int vrow8 = (lane & 7) + ((lane >> 3) & 1) * 8;
            int vc8 = (lane >> 4) << 3;
#pragma unroll
            for (int ks = 0; ks < 4; ks++) {   // key 16-blocks
                uint32_t a0 = packbf(sfr[2 * ks][0],     sfr[2 * ks][1]);
                uint32_t a1 = packbf(sfr[2 * ks][2],     sfr[2 * ks][3]);
                uint32_t a2 = packbf(sfr[2 * ks + 1][0], sfr[2 * ks + 1][1]);
                uint32_t a3 = packbf(sfr[2 * ks + 1][2], sfr[2 * ks + 1][3]);
#pragma unroll
                for (int fp = 0; fp < 4; fp++) {   // dk 16-col pairs
                    uint32_t v0, v1, v2, v3;
                    // m0={k lo,n lo} m1={k hi,n lo} m2={k lo,n hi} m3={k hi,n hi}
                    ldmx4t(v0, v1, v2, v3,
                           s2u(Vt + (ks * 16 + vrow8) * AALD + fp * 16 + vc8));
                    mma16816(ofr[2 * fp][0], ofr[2 * fp][1], ofr[2 * fp][2], ofr[2 * fp][3],
                             a0, a1, a2, a3, v0, v1);
                    mma16816(ofr[2 * fp + 1][0], ofr[2 * fp + 1][1], ofr[2 * fp + 1][2], ofr[2 * fp + 1][3],
                             a0, a1, a2, a3, v2, v3);
                }
            }
        }
    }

    // final l reduction across quad
    l0 += __shfl_xor_sync(0xffffffffu, l0, 1);
    l0 += __shfl_xor_sync(0xffffffffu, l0, 2);
    l1 += __shfl_xor_sync(0xffffffffu, l1, 1);
    l1 += __shfl_xor_sync(0xffffffffu, l1, 2);
    float inv0 = 1.f / l0, inv1 = 1.f / l1;

    // epilogue: ctx[b, q0+row, h*64+col]
    const int b = bh >> 4, h = bh & 15;
    int row0 = q0 + warp * 16 + (lane >> 2);
    int colb = h * DK + 2 * (lane & 3);
#pragma unroll
    for (int f = 0; f < 8; f++) {
        *(__nv_bfloat162*)(g_ctxb + (size_t)(b * SEQ + row0) * DMODEL + colb + f * 8) =
            __float22bfloat162_rn(make_float2(ofr[f][0] * inv0, ofr[f][1] * inv0));
        *(__nv_bfloat162*)(g_ctxb + (size_t)(b * SEQ + row0 + 8) * DMODEL + colb + f * 8) =
            __float22bfloat162_rn(make_float2(ofr[f][2] * inv1, ofr[f][3] * inv1));
    }
}

// ---------------- residual + LayerNorm ---------------------------------------
__global__ void __launch_bounds__(256)
ln_kernel(const float* __restrict__ residual, const float* __restrict__ gamma,
          const float* __restrict__ beta, float* __restrict__ out) {
    const int row = blockIdx.x;
    const int t = threadIdx.x;
    const size_t base = (size_t)row * DMODEL + t * 4;

    float4 r4 = *(const float4*)(residual + base);
    float4 p4 = *(const float4*)(g_proj + base);
    float x0 = r4.x + p4.x, x1 = r4.y + p4.y, x2 = r4.z + p4.z, x3 = r4.w + p4.w;

    float s = x0 + x1 + x2 + x3;
    float ss = x0 * x0 + x1 * x1 + x2 * x2 + x3 * x3;
#pragma unroll
    for (int off = 16; off > 0; off >>= 1) {
        s += __shfl_xor_sync(0xffffffffu, s, off);
        ss += __shfl_xor_sync(0xffffffffu, ss, off);
    }
    __shared__ float rs[8], rss[8], stat[2];
    int w = t >> 5, lane = t & 31;
    if (lane == 0) { rs[w] = s; rss[w] = ss; }
    __syncthreads();
    if (t == 0) {
        float S = 0.f, SS = 0.f;
#pragma unroll
        for (int i = 0; i < 8; i++) { S += rs[i]; SS += rss[i]; }
        float mean = S * (1.f / DMODEL);
        float var = SS * (1.f / DMODEL) - mean * mean;
        stat[0] = mean;
        stat[1] = rsqrtf(var + 1e-5f);
    }
    __syncthreads();
    float mean = stat[0], inv = stat[1];

    float4 g4 = *(const float4*)(gamma + t * 4);
    float4 b4 = *(const float4*)(beta + t * 4);
    float4 y;
    y.x = (x0 - mean) * inv * g4.x + b4.x;
    y.y = (x1 - mean) * inv * g4.y + b4.y;
    y.z = (x2 - mean) * inv * g4.z + b4.z;
    y.w = (x3 - mean) * inv * g4.w + b4.w;
    *(float4*)(out + base) = y;
}

// ---------------- launch ------------------------------------------------------
extern "C" void kernel_launch(void* const* d_in, const int* in_sizes, int n_in,
                              void* d_out, int out_size) {
    const float* query = (const float*)d_in[0];
    const float* key   = (const float*)d_in[1];
    const float* value = (const float*)d_in[2];
    const float* Wq    = (const float*)d_in[3];
    const float* bq    = (const float*)d_in[4];
    const float* Wk    = (const float*)d_in[5];
    const float* bk    = (const float*)d_in[6];
    const float* Wv    = (const float*)d_in[7];
    const float* bv    = (const float*)d_in[8];
    const float* Wo    = (const float*)d_in[9];
    const float* bo    = (const float*)d_in[10];
    const float* gamma = (const float*)d_in[11];
    const float* beta  = (const float*)d_in[12];
    float* out = (float*)d_out;

    static bool attr_done = false;
    if (!attr_done) {
        (void)cudaFuncSetAttribute(gemm_bf16,
                                   cudaFuncAttributeMaxDynamicSharedMemorySize, GEMM_SMEM);
        (void)cudaFuncSetAttribute(attn_kernel,
                                   cudaFuncAttributeMaxDynamicSharedMemorySize, ATTN_SMEM);
        attr_done = true;
    }

    static __nv_bfloat16 *xb = nullptr, *kb, *vb, *wqb, *wkb, *wvb, *wob, *ctxb;
    if (!xb) {
        cudaGetSymbolAddress((void**)&xb,   g_xb);
        cudaGetSymbolAddress((void**)&kb,   g_kb);
        cudaGetSymbolAddress((void**)&vb,   g_vb);
        cudaGetSymbolAddress((void**)&wqb,  g_Wqb);
        cudaGetSymbolAddress((void**)&wkb,  g_Wkb);
        cudaGetSymbolAddress((void**)&wvb,  g_Wvb);
        cudaGetSymbolAddress((void**)&wob,  g_Wob);
        cudaGetSymbolAddress((void**)&ctxb, g_ctxb);
    }

    const int n4_act = MTOT * DMODEL / 4;
    const int n4_w   = DMODEL * DMODEL / 4;
    f2b_kernel<<<n4_act / 256, 256>>>(query, xb, n4_act);
    f2b_kernel<<<n4_act / 256, 256>>>(key,   kb, n4_act);
    f2b_kernel<<<n4_act / 256, 256>>>(value, vb, n4_act);
    f2b_kernel<<<n4_w / 256, 256>>>(Wq, wqb, n4_w);
    f2b_kernel<<<n4_w / 256, 256>>>(Wk, wkb, n4_w);
    f2b_kernel<<<n4_w / 256, 256>>>(Wv, wvb, n4_w);
    f2b_kernel<<<n4_w / 256, 256>>>(Wo, wob, n4_w);
    fill_bias_rep<<<256, 256>>>(bq, bk, bv, bo);

    dim3 ggrid(DMODEL / GBN, MTOT / GBM);   // (8, 64)
    gemm_bf16<<<ggrid, 256, GEMM_SMEM>>>(xb, wqb, 0, 0);
    gemm_bf16<<<ggrid, 256, GEMM_SMEM>>>(kb, wkb, 1, 1);
    gemm_bf16<<<ggrid, 256, GEMM_SMEM>>>(vb, wvb, 2, 2);

    dim3 agrid(SEQ / AQT, BATCH * NHEADS);  // (16, 64)
    attn_kernel<<<agrid, 256, ATTN_SMEM>>>();

    gemm_bf16<<<ggrid, 256, GEMM_SMEM>>>(ctxb, wob, 3, 3);

    ln_kernel<<<MTOT, 256>>>(query, gamma, beta, out);
}

// round 12
// speedup vs baseline: 5.7261x; 1.3120x over previous
#include <cuda_runtime.h>
#include <cuda_bf16.h>
#include <cstdint>

#define BATCH 4
#define SEQ 2048
#define DMODEL 1024
#define NHEADS 16
#define DK 64
#define MTOT (BATCH * SEQ)   // 8192

// ---------------- scratch ----------------------------------------------------
__device__ __nv_bfloat16 g_xb[MTOT * DMODEL];
__device__ __nv_bfloat16 g_kb[MTOT * DMODEL];
__device__ __nv_bfloat16 g_vb[MTOT * DMODEL];
__device__ __nv_bfloat16 g_Wqb[DMODEL * DMODEL];
__device__ __nv_bfloat16 g_Wkb[DMODEL * DMODEL];
__device__ __nv_bfloat16 g_Wvb[DMODEL * DMODEL];
__device__ __nv_bfloat16 g_Wob[DMODEL * DMODEL];
__device__ __nv_bfloat16 g_Qb[BATCH * NHEADS * SEQ * DK];   // [B,H,S,DK]
__device__ __nv_bfloat16 g_Kb[BATCH * NHEADS * SEQ * DK];
__device__ __nv_bfloat16 g_Vb[BATCH * NHEADS * SEQ * DK];
__device__ __nv_bfloat16 g_ctxb[MTOT * DMODEL];
__device__ float g_proj[MTOT * DMODEL];

// ---------------- converts ----------------------------------------------------
__global__ void __launch_bounds__(256)
f2b_kernel(const float* __restrict__ src, __nv_bfloat16* __restrict__ dst, int n4) {
    int i = blockIdx.x * blockDim.x + threadIdx.x;
    if (i >= n4) return;
    float4 v = ((const float4*)src)[i];
    ((__nv_bfloat162*)dst)[2 * i]     = __float22bfloat162_rn(make_float2(v.x, v.y));
    ((__nv_bfloat162*)dst)[2 * i + 1] = __float22bfloat162_rn(make_float2(v.z, v.w));
}

// ---------------- PTX helpers -------------------------------------------------
__device__ __forceinline__ void cp_async16(void* smem_dst, const void* gmem_src) {
    unsigned int a = (unsigned int)__cvta_generic_to_shared(smem_dst);
    asm volatile("cp.async.cg.shared.global [%0], [%1], 16;\n" :: "r"(a), "l"(gmem_src));
}
#define CP_COMMIT() asm volatile("cp.async.commit_group;\n" ::: "memory")
#define CP_WAIT0()  asm volatile("cp.async.wait_group 0;\n" ::: "memory")

__device__ __forceinline__ unsigned int s2u(const void* p) {
    return (unsigned int)__cvta_generic_to_shared(p);
}
__device__ __forceinline__ void ldmx4(uint32_t& r0, uint32_t& r1, uint32_t& r2, uint32_t& r3,
                                      unsigned int a) {
    asm volatile("ldmatrix.sync.aligned.m8n8.x4.shared.b16 {%0,%1,%2,%3},[%4];"
                 : "=r"(r0), "=r"(r1), "=r"(r2), "=r"(r3) : "r"(a));
}
__device__ __forceinline__ void ldmx4t(uint32_t& r0, uint32_t& r1, uint32_t& r2, uint32_t& r3,
                                       unsigned int a) {
    asm volatile("ldmatrix.sync.aligned.m8n8.x4.trans.shared.b16 {%0,%1,%2,%3},[%4];"
                 : "=r"(r0), "=r"(r1), "=r"(r2), "=r"(r3) : "r"(a));
}
__device__ __forceinline__ void mma16816(float& d0, float& d1, float& d2, float& d3,
                                         uint32_t a0, uint32_t a1, uint32_t a2, uint32_t a3,
                                         uint32_t b0, uint32_t b1) {
    asm volatile(
        "mma.sync.aligned.m16n8k16.row.col.f32.bf16.bf16.f32 "
        "{%0,%1,%2,%3}, {%4,%5,%6,%7}, {%8,%9}, {%0,%1,%2,%3};"
        : "+f"(d0), "+f"(d1), "+f"(d2), "+f"(d3)
        : "r"(a0), "r"(a1), "r"(a2), "r"(a3), "r"(b0), "r"(b1));
}
__device__ __forceinline__ float fexp2(float x) {
    float y;
    asm("ex2.approx.ftz.f32 %0, %1;" : "=f"(y) : "f"(x));
    return y;
}
__device__ __forceinline__ uint32_t packbf(float a, float b) {
    __nv_bfloat162 t = __float22bfloat162_rn(make_float2(a, b));
    return *reinterpret_cast<uint32_t*>(&t);
}

// ---------------- bf16 GEMM: raw mma.sync, warp tile 64x64 --------------------
// Block 128x128, BK=64, 4 warps (2x2). Per warp per k16: 4 ldmx4 + 4 ldmx4t
// feed 32 mma16816 (ld:mma = 1:4). 2-stage cp.async pipeline, 2 CTAs/SM.
// out_sel 0/1/2: bf16 scatter to g_Qb/g_Kb/g_Vb [B,H,S,DK]; 3: f32 g_proj.
#define GBM 128
#define GBN 128
#define GBK 64
#define GLDA 72      // bf16/row (144 B)
#define GLDB 136     // bf16/row (272 B)
#define GEMM_SMEM (2 * (GBM * GLDA + GBK * GLDB) * 2)   // 71680 B
#define NKT (DMODEL / GBK)                              // 16

__global__ void __launch_bounds__(128, 2)
gemm_bf16(const __nv_bfloat16* __restrict__ A, const __nv_bfloat16* __restrict__ W,
          const float* __restrict__ bias, int out_sel) {
    extern __shared__ __align__(16) char smraw[];
    __nv_bfloat16* As[2] = { (__nv_bfloat16*)smraw,
                             (__nv_bfloat16*)smraw + GBM * GLDA };
    __nv_bfloat16* Bs[2] = { (__nv_bfloat16*)smraw + 2 * GBM * GLDA,
                             (__nv_bfloat16*)smraw + 2 * GBM * GLDA + GBK * GLDB };

    const int t = threadIdx.x;
    const int lane = t & 31;
    const int warp = t >> 5;        // 0..3
    const int wm = warp >> 1;       // 0..1 (M)
    const int wn = warp & 1;        // 0..1 (N)
    const int row0 = blockIdx.y * GBM;
    const int col0 = blockIdx.x * GBN;

    // accumulators: d[mf][nf][e], mf: 4 x m16, nf: 8 x n8
    float d[4][8][4];
    {
        const int cb = col0 + wn * 64 + 2 * (lane & 3);
#pragma unroll
        for (int nf = 0; nf < 8; nf++) {
            float b0 = bias[cb + nf * 8];
            float b1 = bias[cb + nf * 8 + 1];
#pragma unroll
            for (int mf = 0; mf < 4; mf++) {
                d[mf][nf][0] = b0; d[mf][nf][1] = b1;
                d[mf][nf][2] = b0; d[mf][nf][3] = b1;
            }
        }
    }

    // stage 0: A 128x64 (1024 16B chunks), B 64x128 (1024 chunks); 8+8 per thread
    {
#pragma unroll
        for (int i = 0; i < 8; i++) {
            int idx = t + i * 128;
            int r = idx >> 3, v = idx & 7;
            cp_async16(As[0] + r * GLDA + v * 8, A + (size_t)(row0 + r) * DMODEL + v * 8);
        }
#pragma unroll
        for (int i = 0; i < 8; i++) {
            int idx = t + i * 128;
            int r = idx >> 4, v = idx & 15;
            cp_async16(Bs[0] + r * GLDB + v * 8, W + (size_t)r * DMODEL + col0 + v * 8);
        }
        CP_COMMIT();
    }

    const int lrow = lane & 15;
    const int lcol8 = (lane >> 4) << 3;

    for (int kt = 0; kt < NKT; kt++) {
        const int buf = kt & 1;
        CP_WAIT0();
        __syncthreads();
        if (kt + 1 < NKT) {
            const int k1 = (kt + 1) * GBK;
#pragma unroll
            for (int i = 0; i < 8; i++) {
                int idx = t + i * 128;
                int r = idx >> 3, v = idx & 7;
                cp_async16(As[buf ^ 1] + r * GLDA + v * 8,
                           A + (size_t)(row0 + r) * DMODEL + k1 + v * 8);
            }
#pragma unroll
            for (int i = 0; i < 8; i++) {
                int idx = t + i * 128;
                int r = idx >> 4, v = idx & 15;
                cp_async16(Bs[buf ^ 1] + r * GLDB + v * 8,
                           W + (size_t)(k1 + r) * DMODEL + col0 + v * 8);
            }
            CP_COMMIT();
        }

        const __nv_bfloat16* At = As[buf];
        const __nv_bfloat16* Bt = Bs[buf];
#pragma unroll
        for (int ks = 0; ks < GBK / 16; ks++) {
            uint32_t af[4][4];
#pragma unroll
            for (int mf = 0; mf < 4; mf++)
                ldmx4(af[mf][0], af[mf][1], af[mf][2], af[mf][3],
                      s2u(At + (wm * 64 + mf * 16 + lrow) * GLDA + ks * 16 + lcol8));
#pragma unroll
            for (int nf16 = 0; nf16 < 4; nf16++) {
                uint32_t b0, b1, b2, b3;
                // trans: m0={k lo,n lo} m1={k hi,n lo} m2={k lo,n hi} m3={k hi,n hi}
                ldmx4t(b0, b1, b2, b3,
                       s2u(Bt + (ks * 16 + lrow) * GLDB + wn * 64 + nf16 * 16 + lcol8));
#pragma unroll
                for (int mf = 0; mf < 4; mf++) {
                    mma16816(d[mf][2 * nf16][0], d[mf][2 * nf16][1],
                             d[mf][2 * nf16][2], d[mf][2 * nf16][3],
                             af[mf][0], af[mf][1], af[mf][2], af[mf][3], b0, b1);
                    mma16816(d[mf][2 * nf16 + 1][0], d[mf][2 * nf16 + 1][1],
                             d[mf][2 * nf16 + 1][2], d[mf][2 * nf16 + 1][3],
                             af[mf][0], af[mf][1], af[mf][2], af[mf][3], b2, b3);
                }
            }
        }
        __syncthreads();
    }

    // epilogue: direct register stores
    const int rbase = row0 + wm * 64 + (lane >> 2);
    const int cb2 = wn * 64 + 2 * (lane & 3);
    if (out_sel <= 2) {
        __nv_bfloat16* outb = (out_sel == 0) ? g_Qb : (out_sel == 1) ? g_Kb : g_Vb;
#pragma unroll
        for (int mf = 0; mf < 4; mf++) {
#pragma unroll
            for (int half = 0; half < 2; half++) {
                int gr = rbase + mf * 16 + half * 8;
                int b = gr >> 11, s0 = gr & (SEQ - 1);
#pragma unroll
                for (int nf = 0; nf < 8; nf++) {
                    int gc = col0 + cb2 + nf * 8;
                    int h = gc >> 6, d0 = gc & (DK - 1);
                    *(__nv_bfloat162*)(outb + ((size_t)(b * NHEADS + h) * SEQ + s0) * DK + d0) =
                        __float22bfloat162_rn(
                            make_float2(d[mf][nf][2 * half], d[mf][nf][2 * half + 1]));
                }
            }
        }
    } else {
#pragma unroll
        for (int mf = 0; mf < 4; mf++) {
#pragma unroll
            for (int half = 0; half < 2; half++) {
                int gr = rbase + mf * 16 + half * 8;
#pragma unroll
                for (int nf = 0; nf < 8; nf++) {
                    int gc = col0 + cb2 + nf * 8;
                    *(float2*)(g_proj + (size_t)gr * DMODEL + gc) =
                        make_float2(d[mf][nf][2 * half], d[mf][nf][2 * half + 1]);
                }
            }
        }
    }
}

// ---------------- Flash attention v3: QT=128, 8 warps, ldmatrix.x4 ------------
#define AQT 128
#define AKT 64
#define AALD 72
#define ATTN_SMEM ((AQT * AALD + 4 * AKT * AALD) * 2)   // 55296 B

__global__ void __launch_bounds__(256, 2)
attn_kernel() {
    extern __shared__ __align__(16) char smraw[];
    __nv_bfloat16* Qs = (__nv_bfloat16*)smraw;
    __nv_bfloat16* Ks0 = Qs + AQT * AALD;
    __nv_bfloat16* Vs0 = Ks0 + 2 * AKT * AALD;
    __nv_bfloat16* Ksb[2] = { Ks0, Ks0 + AKT * AALD };
    __nv_bfloat16* Vsb[2] = { Vs0, Vs0 + AKT * AALD };

    const int t = threadIdx.x;
    const int lane = t & 31;
    const int warp = t >> 5;
    const int q0 = blockIdx.x * AQT;
    const int bh = blockIdx.y;
    const __nv_bfloat16* Qg = g_Qb + (size_t)bh * SEQ * DK;
    const __nv_bfloat16* Kg = g_Kb + (size_t)bh * SEQ * DK;
    const __nv_bfloat16* Vg = g_Vb + (size_t)bh * SEQ * DK;

#pragma unroll
    for (int i = 0; i < 2; i++) {
        int idx = t + i * 256;
        int r = idx >> 3, v = idx & 7;
        cp_async16(Ksb[0] + r * AALD + v * 8, Kg + (size_t)r * DK + v * 8);
        cp_async16(Vsb[0] + r * AALD + v * 8, Vg + (size_t)r * DK + v * 8);
    }
    CP_COMMIT();

#pragma unroll
    for (int i = 0; i < 4; i++) {
        int idx = t + i * 256;
        int r = idx >> 3, v = idx & 7;
        *(uint4*)(Qs + r * AALD + v * 8) = *(const uint4*)(Qg + (size_t)(q0 + r) * DK + v * 8);
    }
    __syncthreads();

    uint32_t qa[4][4];
    {
        int row = warp * 16 + (lane & 15);
        int col8 = (lane >> 4) << 3;
#pragma unroll
        for (int ks = 0; ks < 4; ks++)
            ldmx4(qa[ks][0], qa[ks][1], qa[ks][2], qa[ks][3],
                  s2u(Qs + row * AALD + ks * 16 + col8));
    }

    float ofr[8][4];
#pragma unroll
    for (int f = 0; f < 8; f++)
#pragma unroll
        for (int e = 0; e < 4; e++) ofr[f][e] = 0.f;
    float mt0 = -1e30f, mt1 = -1e30f, l0 = 0.f, l1 = 0.f;

    const float CS = 0.125f * 1.4426950408889634f;

    const int NTILE = SEQ / AKT;
    for (int kt = 0; kt < NTILE; kt++) {
        const int buf = kt & 1;
        CP_WAIT0();
        __syncthreads();
        if (kt + 1 < NTILE) {
            const __nv_bfloat16* Kn = Kg + (size_t)(kt + 1) * AKT * DK;
            const __nv_bfloat16* Vn = Vg + (size_t)(kt + 1) * AKT * DK;
#pragma unroll
            for (int i = 0; i < 2; i++) {
                int idx = t + i * 256;
                int r = idx >> 3, v = idx & 7;
                cp_async16(Ksb[buf ^ 1] + r * AALD + v * 8, Kn + (size_t)r * DK + v * 8);
                cp_async16(Vsb[buf ^ 1] + r * AALD + v * 8, Vn + (size_t)r * DK + v * 8);
            }
            CP_COMMIT();
        }

        float sfr[8][4];
#pragma unroll
        for (int f = 0; f < 8; f++)
#pragma unroll
            for (int e = 0; e < 4; e++) sfr[f][e] = 0.f;

        {
            const __nv_bfloat16* Kt = Ksb[buf];
            int krow = (lane & 15);
            int kc8 = (lane >> 4) << 3;
#pragma unroll
            for (int ks = 0; ks < 4; ks++) {
#pragma unroll
                for (int fb = 0; fb < 4; fb++) {
                    uint32_t k0, k1, k2, k3;
                    ldmx4(k0, k1, k2, k3,
                          s2u(Kt + (fb * 16 + krow) * AALD + ks * 16 + kc8));
                    mma16816(sfr[2 * fb][0], sfr[2 * fb][1], sfr[2 * fb][2], sfr[2 * fb][3],
                             qa[ks][0], qa[ks][1], qa[ks][2], qa[ks][3], k0, k2);
                    mma16816(sfr[2 * fb + 1][0], sfr[2 * fb + 1][1], sfr[2 * fb + 1][2], sfr[2 * fb + 1][3],
                             qa[ks][0], qa[ks][1], qa[ks][2], qa[ks][3], k1, k3);
                }
            }
        }

        float mx0 = -1e30f, mx1 = -1e30f;
#pragma unroll
        for (int f = 0; f < 8; f++) {
            sfr[f][0] *= CS; sfr[f][1] *= CS; sfr[f][2] *= CS; sfr[f][3] *= CS;
            mx0 = fmaxf(mx0, fmaxf(sfr[f][0], sfr[f][1]));
            mx1 = fmaxf(mx1, fmaxf(sfr[f][2], sfr[f][3]));
        }
        mx0 = fmaxf(mx0, __shfl_xor_sync(0xffffffffu, mx0, 1));
        mx0 = fmaxf(mx0, __shfl_xor_sync(0xffffffffu, mx0, 2));
        mx1 = fmaxf(mx1, __shfl_xor_sync(0xffffffffu, mx1, 1));
        mx1 = fmaxf(mx1, __shfl_xor_sync(0xffffffffu, mx1, 2));
        float m0n = fmaxf(mt0, mx0), m1n = fmaxf(mt1, mx1);
        float al0 = fexp2(mt0 - m0n), al1 = fexp2(mt1 - m1n);
        mt0 = m0n; mt1 = m1n;

        float ps0 = 0.f, ps1 = 0.f;
#pragma unroll
        for (int f = 0; f < 8; f++) {
            sfr[f][0] = fexp2(sfr[f][0] - m0n);
            sfr[f][1] = fexp2(sfr[f][1] - m0n);
            sfr[f][2] = fexp2(sfr[f][2] - m1n);
            sfr[f][3] = fexp2(sfr[f][3] - m1n);
            ps0 += sfr[f][0] + sfr[f][1];
            ps1 += sfr[f][2] + sfr[f][3];
        }
        l0 = l0 * al0 + ps0;
        l1 = l1 * al1 + ps1;

#pragma unroll
        for (int f = 0; f < 8; f++) {
            ofr[f][0] *= al0; ofr[f][1] *= al0;
            ofr[f][2] *= al1; ofr[f][3] *= al1;
        }

        {
            const __nv_bfloat16* Vt = Vsb[buf];
            int vrow = (lane & 15);
            int vc8 = (lane >> 4) << 3;
#pragma unroll
            for (int ks = 0; ks < 4; ks++) {
                uint32_t a0 = packbf(sfr[2 * ks][0],     sfr[2 * ks][1]);
                uint32_t a1 = packbf(sfr[2 * ks][2],     sfr[2 * ks][3]);
                uint32_t a2 = packbf(sfr[2 * ks + 1][0], sfr[2 * ks + 1][1]);
                uint32_t a3 = packbf(sfr[2 * ks + 1][2], sfr[2 * ks + 1][3]);
#pragma unroll
                for (int fp = 0; fp < 4; fp++) {
                    uint32_t v0, v1, v2, v3;
                    ldmx4t(v0, v1, v2, v3,
                           s2u(Vt + (ks * 16 + vrow) * AALD + fp * 16 + vc8));
                    mma16816(ofr[2 * fp][0], ofr[2 * fp][1], ofr[2 * fp][2], ofr[2 * fp][3],
                             a0, a1, a2, a3, v0, v1);
                    mma16816(ofr[2 * fp + 1][0], ofr[2 * fp + 1][1], ofr[2 * fp + 1][2], ofr[2 * fp + 1][3],
                             a0, a1, a2, a3, v2, v3);
                }
            }
        }
    }

    l0 += __shfl_xor_sync(0xffffffffu, l0, 1);
    l0 += __shfl_xor_sync(0xffffffffu, l0, 2);
    l1 += __shfl_xor_sync(0xffffffffu, l1, 1);
    l1 += __shfl_xor_sync(0xffffffffu, l1, 2);
    float inv0 = 1.f / l0, inv1 = 1.f / l1;

    const int b = bh >> 4, h = bh & 15;
    int row0 = q0 + warp * 16 + (lane >> 2);
    int colb = h * DK + 2 * (lane & 3);
#pragma unroll
    for (int f = 0; f < 8; f++) {
        *(__nv_bfloat162*)(g_ctxb + (size_t)(b * SEQ + row0) * DMODEL + colb + f * 8) =
            __float22bfloat162_rn(make_float2(ofr[f][0] * inv0, ofr[f][1] * inv0));
        *(__nv_bfloat162*)(g_ctxb + (size_t)(b * SEQ + row0 + 8) * DMODEL + colb + f * 8) =
            __float22bfloat162_rn(make_float2(ofr[f][2] * inv1, ofr[f][3] * inv1));
    }
}

// ---------------- residual + LayerNorm ---------------------------------------
__global__ void __launch_bounds__(256)
ln_kernel(const float* __restrict__ residual, const float* __restrict__ gamma,
          const float* __restrict__ beta, float* __restrict__ out) {
    const int row = blockIdx.x;
    const int t = threadIdx.x;
    const size_t base = (size_t)row * DMODEL + t * 4;

    float4 r4 = *(const float4*)(residual + base);
    float4 p4 = *(const float4*)(g_proj + base);
    float x0 = r4.x + p4.x, x1 = r4.y + p4.y, x2 = r4.z + p4.z, x3 = r4.w + p4.w;

    float s = x0 + x1 + x2 + x3;
    float ss = x0 * x0 + x1 * x1 + x2 * x2 + x3 * x3;
#pragma unroll
    for (int off = 16; off > 0; off >>= 1) {
        s += __shfl_xor_sync(0xffffffffu, s, off);
        ss += __shfl_xor_sync(0xffffffffu, ss, off);
    }
    __shared__ float rs[8], rss[8], stat[2];
    int w = t >> 5, lane = t & 31;
    if (lane == 0) { rs[w] = s; rss[w] = ss; }
    __syncthreads();
    if (t == 0) {
        float S = 0.f, SS = 0.f;
#pragma unroll
        for (int i = 0; i < 8; i++) { S += rs[i]; SS += rss[i]; }
        float mean = S * (1.f / DMODEL);
        float var = SS * (1.f / DMODEL) - mean * mean;
        stat[0] = mean;
        stat[1] = rsqrtf(var + 1e-5f);
    }
    __syncthreads();
    float mean = stat[0], inv = stat[1];

    float4 g4 = *(const float4*)(gamma + t * 4);
    float4 b4 = *(const float4*)(beta + t * 4);
    float4 y;
    y.x = (x0 - mean) * inv * g4.x + b4.x;
    y.y = (x1 - mean) * inv * g4.y + b4.y;
    y.z = (x2 - mean) * inv * g4.z + b4.z;
    y.w = (x3 - mean) * inv * g4.w + b4.w;
    *(float4*)(out + base) = y;
}

// ---------------- launch ------------------------------------------------------
extern "C" void kernel_launch(void* const* d_in, const int* in_sizes, int n_in,
                              void* d_out, int out_size) {
    const float* query = (const float*)d_in[0];
    const float* key   = (const float*)d_in[1];
    const float* value = (const float*)d_in[2];
    const float* Wq    = (const float*)d_in[3];
    const float* bq    = (const float*)d_in[4];
    const float* Wk    = (const float*)d_in[5];
    const float* bk    = (const float*)d_in[6];
    const float* Wv    = (const float*)d_in[7];
    const float* bv    = (const float*)d_in[8];
    const float* Wo    = (const float*)d_in[9];
    const float* bo    = (const float*)d_in[10];
    const float* gamma = (const float*)d_in[11];
    const float* beta  = (const float*)d_in[12];
    float* out = (float*)d_out;

    static bool attr_done = false;
    if (!attr_done) {
        (void)cudaFuncSetAttribute(gemm_bf16,
                                   cudaFuncAttributeMaxDynamicSharedMemorySize, GEMM_SMEM);
        (void)cudaFuncSetAttribute(attn_kernel,
                                   cudaFuncAttributeMaxDynamicSharedMemorySize, ATTN_SMEM);
        attr_done = true;
    }

    static __nv_bfloat16 *xb = nullptr, *kb, *vb, *wqb, *wkb, *wvb, *wob, *ctxb;
    if (!xb) {
        cudaGetSymbolAddress((void**)&xb,   g_xb);
        cudaGetSymbolAddress((void**)&kb,   g_kb);
        cudaGetSymbolAddress((void**)&vb,   g_vb);
        cudaGetSymbolAddress((void**)&wqb,  g_Wqb);
        cudaGetSymbolAddress((void**)&wkb,  g_Wkb);
        cudaGetSymbolAddress((void**)&wvb,  g_Wvb);
        cudaGetSymbolAddress((void**)&wob,  g_Wob);
        cudaGetSymbolAddress((void**)&ctxb, g_ctxb);
    }

    const int n4_act = MTOT * DMODEL / 4;
    const int n4_w   = DMODEL * DMODEL / 4;
    f2b_kernel<<<n4_act / 256, 256>>>(query, xb, n4_act);
    f2b_kernel<<<n4_act / 256, 256>>>(key,   kb, n4_act);
    f2b_kernel<<<n4_act / 256, 256>>>(value, vb, n4_act);
    f2b_kernel<<<n4_w / 256, 256>>>(Wq, wqb, n4_w);
    f2b_kernel<<<n4_w / 256, 256>>>(Wk, wkb, n4_w);
    f2b_kernel<<<n4_w / 256, 256>>>(Wv, wvb, n4_w);
    f2b_kernel<<<n4_w / 256, 256>>>(Wo, wob, n4_w);

    dim3 ggrid(DMODEL / GBN, MTOT / GBM);   // (8, 64)
    gemm_bf16<<<ggrid, 128, GEMM_SMEM>>>(xb, wqb, bq, 0);
    gemm_bf16<<<ggrid, 128, GEMM_SMEM>>>(kb, wkb, bk, 1);
    gemm_bf16<<<ggrid, 128, GEMM_SMEM>>>(vb, wvb, bv, 2);

    dim3 agrid(SEQ / AQT, BATCH * NHEADS);  // (16, 64)
    attn_kernel<<<agrid, 256, ATTN_SMEM>>>();

    gemm_bf16<<<ggrid, 128, GEMM_SMEM>>>(ctxb, wob, bo, 3);

    ln_kernel<<<MTOT, 256>>>(query, gamma, beta, out);
}

// round 14
// speedup vs baseline: 6.0622x; 1.0587x over previous
#include <cuda_runtime.h>
#include <cuda_bf16.h>
#include <cstdint>

#define BATCH 4
#define SEQ 2048
#define DMODEL 1024
#define NHEADS 16
#define DK 64
#define MTOT (BATCH * SEQ)   // 8192

// ---------------- scratch ----------------------------------------------------
__device__ __nv_bfloat16 g_xb[MTOT * DMODEL];
__device__ __nv_bfloat16 g_kb[MTOT * DMODEL];
__device__ __nv_bfloat16 g_vb[MTOT * DMODEL];
__device__ __nv_bfloat16 g_Wqb[DMODEL * DMODEL];
__device__ __nv_bfloat16 g_Wkb[DMODEL * DMODEL];
__device__ __nv_bfloat16 g_Wvb[DMODEL * DMODEL];
__device__ __nv_bfloat16 g_Wob[DMODEL * DMODEL];
__device__ __nv_bfloat16 g_Qb[BATCH * NHEADS * SEQ * DK];   // [B,H,S,DK]
__device__ __nv_bfloat16 g_Kb[BATCH * NHEADS * SEQ * DK];
__device__ __nv_bfloat16 g_Vb[BATCH * NHEADS * SEQ * DK];
__device__ __nv_bfloat16 g_ctxb[MTOT * DMODEL];
__device__ float g_proj[MTOT * DMODEL];

// ---------------- converts (fused, z-indexed) ---------------------------------
__global__ void __launch_bounds__(256)
f2b3_kernel(const float* __restrict__ q, const float* __restrict__ k,
            const float* __restrict__ v) {
    const int z = blockIdx.z;
    const float* src = (z == 0) ? q : (z == 1) ? k : v;
    __nv_bfloat16* dst = (z == 0) ? g_xb : (z == 1) ? g_kb : g_vb;
    int i = blockIdx.x * blockDim.x + threadIdx.x;
    float4 val = ((const float4*)src)[i];
    ((__nv_bfloat162*)dst)[2 * i]     = __float22bfloat162_rn(make_float2(val.x, val.y));
    ((__nv_bfloat162*)dst)[2 * i + 1] = __float22bfloat162_rn(make_float2(val.z, val.w));
}

__global__ void __launch_bounds__(256)
f2b4_kernel(const float* __restrict__ wq, const float* __restrict__ wk,
            const float* __restrict__ wv, const float* __restrict__ wo) {
    const int z = blockIdx.z;
    const float* src = (z == 0) ? wq : (z == 1) ? wk : (z == 2) ? wv : wo;
    __nv_bfloat16* dst = (z == 0) ? g_Wqb : (z == 1) ? g_Wkb : (z == 2) ? g_Wvb : g_Wob;
    int i = blockIdx.x * blockDim.x + threadIdx.x;
    float4 val = ((const float4*)src)[i];
    ((__nv_bfloat162*)dst)[2 * i]     = __float22bfloat162_rn(make_float2(val.x, val.y));
    ((__nv_bfloat162*)dst)[2 * i + 1] = __float22bfloat162_rn(make_float2(val.z, val.w));
}

// ---------------- PTX helpers -------------------------------------------------
__device__ __forceinline__ void cp_async16(void* smem_dst, const void* gmem_src) {
    unsigned int a = (unsigned int)__cvta_generic_to_shared(smem_dst);
    asm volatile("cp.async.cg.shared.global [%0], [%1], 16;\n" :: "r"(a), "l"(gmem_src));
}
#define CP_COMMIT() asm volatile("cp.async.commit_group;\n" ::: "memory")
#define CP_WAIT0()  asm volatile("cp.async.wait_group 0;\n" ::: "memory")

__device__ __forceinline__ unsigned int s2u(const void* p) {
    return (unsigned int)__cvta_generic_to_shared(p);
}
__device__ __forceinline__ void ldmx4(uint32_t& r0, uint32_t& r1, uint32_t& r2, uint32_t& r3,
                                      unsigned int a) {
    asm volatile("ldmatrix.sync.aligned.m8n8.x4.shared.b16 {%0,%1,%2,%3},[%4];"
                 : "=r"(r0), "=r"(r1), "=r"(r2), "=r"(r3) : "r"(a));
}
__device__ __forceinline__ void ldmx4t(uint32_t& r0, uint32_t& r1, uint32_t& r2, uint32_t& r3,
                                       unsigned int a) {
    asm volatile("ldmatrix.sync.aligned.m8n8.x4.trans.shared.b16 {%0,%1,%2,%3},[%4];"
                 : "=r"(r0), "=r"(r1), "=r"(r2), "=r"(r3) : "r"(a));
}
__device__ __forceinline__ void mma16816(float& d0, float& d1, float& d2, float& d3,
                                         uint32_t a0, uint32_t a1, uint32_t a2, uint32_t a3,
                                         uint32_t b0, uint32_t b1) {
    asm volatile(
        "mma.sync.aligned.m16n8k16.row.col.f32.bf16.bf16.f32 "
        "{%0,%1,%2,%3}, {%4,%5,%6,%7}, {%8,%9}, {%0,%1,%2,%3};"
        : "+f"(d0), "+f"(d1), "+f"(d2), "+f"(d3)
        : "r"(a0), "r"(a1), "r"(a2), "r"(a3), "r"(b0), "r"(b1));
}
__device__ __forceinline__ float fexp2(float x) {
    float y;
    asm("ex2.approx.ftz.f32 %0, %1;" : "=f"(y) : "f"(x));
    return y;
}
__device__ __forceinline__ uint32_t packbf(float a, float b) {
    __nv_bfloat162 t = __float22bfloat162_rn(make_float2(a, b));
    return *reinterpret_cast<uint32_t*>(&t);
}

// ---------------- bf16 GEMM core: raw mma.sync, warp tile 64x64 ----------------
#define GBM 128
#define GBN 128
#define GBK 64
#define GLDA 72
#define GLDB 136
#define GEMM_SMEM (2 * (GBM * GLDA + GBK * GLDB) * 2)   // 71680 B
#define NKT (DMODEL / GBK)                              // 16

__device__ __forceinline__ void gemm_core(const __nv_bfloat16* __restrict__ A,
                                          const __nv_bfloat16* __restrict__ W,
                                          const float* __restrict__ bias, int out_sel) {
    extern __shared__ __align__(16) char smraw[];
    __nv_bfloat16* As[2] = { (__nv_bfloat16*)smraw,
                             (__nv_bfloat16*)smraw + GBM * GLDA };
    __nv_bfloat16* Bs[2] = { (__nv_bfloat16*)smraw + 2 * GBM * GLDA,
                             (__nv_bfloat16*)smraw + 2 * GBM * GLDA + GBK * GLDB };

    const int t = threadIdx.x;
    const int lane = t & 31;
    const int warp = t >> 5;
    const int wm = warp >> 1;
    const int wn = warp & 1;
    const int row0 = blockIdx.y * GBM;
    const int col0 = blockIdx.x * GBN;

    float d[4][8][4];
    {
        const int cb = col0 + wn * 64 + 2 * (lane & 3);
#pragma unroll
        for (int nf = 0; nf < 8; nf++) {
            float b0 = bias[cb + nf * 8];
            float b1 = bias[cb + nf * 8 + 1];
#pragma unroll
            for (int mf = 0; mf < 4; mf++) {
                d[mf][nf][0] = b0; d[mf][nf][1] = b1;
                d[mf][nf][2] = b0; d[mf][nf][3] = b1;
            }
        }
    }

    {
#pragma unroll
        for (int i = 0; i < 8; i++) {
            int idx = t + i * 128;
            int r = idx >> 3, v = idx & 7;
            cp_async16(As[0] + r * GLDA + v * 8, A + (size_t)(row0 + r) * DMODEL + v * 8);
        }
#pragma unroll
        for (int i = 0; i < 8; i++) {
            int idx = t + i * 128;
            int r = idx >> 4, v = idx & 15;
            cp_async16(Bs[0] + r * GLDB + v * 8, W + (size_t)r * DMODEL + col0 + v * 8);
        }
        CP_COMMIT();
    }

    const int lrow = lane & 15;
    const int lcol8 = (lane >> 4) << 3;

    for (int kt = 0; kt < NKT; kt++) {
        const int buf = kt & 1;
        CP_WAIT0();
        __syncthreads();
        if (kt + 1 < NKT) {
            const int k1 = (kt + 1) * GBK;
#pragma unroll
            for (int i = 0; i < 8; i++) {
                int idx = t + i * 128;
                int r = idx >> 3, v = idx & 7;
                cp_async16(As[buf ^ 1] + r * GLDA + v * 8,
                           A + (size_t)(row0 + r) * DMODEL + k1 + v * 8);
            }
#pragma unroll
            for (int i = 0; i < 8; i++) {
                int idx = t + i * 128;
                int r = idx >> 4, v = idx & 15;
                cp_async16(Bs[buf ^ 1] + r * GLDB + v * 8,
                           W + (size_t)(k1 + r) * DMODEL + col0 + v * 8);
            }
            CP_COMMIT();
        }

        const __nv_bfloat16* At = As[buf];
        const __nv_bfloat16* Bt = Bs[buf];
#pragma unroll
        for (int ks = 0; ks < GBK / 16; ks++) {
            uint32_t af[4][4];
#pragma unroll
            for (int mf = 0; mf < 4; mf++)
                ldmx4(af[mf][0], af[mf][1], af[mf][2], af[mf][3],
                      s2u(At + (wm * 64 + mf * 16 + lrow) * GLDA + ks * 16 + lcol8));
#pragma unroll
            for (int nf16 = 0; nf16 < 4; nf16++) {
                uint32_t b0, b1, b2, b3;
                ldmx4t(b0, b1, b2, b3,
                       s2u(Bt + (ks * 16 + lrow) * GLDB + wn * 64 + nf16 * 16 + lcol8));
#pragma unroll
                for (int mf = 0; mf < 4; mf++) {
                    mma16816(d[mf][2 * nf16][0], d[mf][2 * nf16][1],
                             d[mf][2 * nf16][2], d[mf][2 * nf16][3],
                             af[mf][0], af[mf][1], af[mf][2], af[mf][3], b0, b1);
                    mma16816(d[mf][2 * nf16 + 1][0], d[mf][2 * nf16 + 1][1],
                             d[mf][2 * nf16 + 1][2], d[mf][2 * nf16 + 1][3],
                             af[mf][0], af[mf][1], af[mf][2], af[mf][3], b2, b3);
                }
            }
        }
        __syncthreads();
    }

    const int rbase = row0 + wm * 64 + (lane >> 2);
    const int cb2 = wn * 64 + 2 * (lane & 3);
    if (out_sel <= 2) {
        __nv_bfloat16* outb = (out_sel == 0) ? g_Qb : (out_sel == 1) ? g_Kb : g_Vb;
#pragma unroll
        for (int mf = 0; mf < 4; mf++) {
#pragma unroll
            for (int half = 0; half < 2; half++) {
                int gr = rbase + mf * 16 + half * 8;
                int b = gr >> 11, s0 = gr & (SEQ - 1);
#pragma unroll
                for (int nf = 0; nf < 8; nf++) {
                    int gc = col0 + cb2 + nf * 8;
                    int h = gc >> 6, d0 = gc & (DK - 1);
                    *(__nv_bfloat162*)(outb + ((size_t)(b * NHEADS + h) * SEQ + s0) * DK + d0) =
                        __float22bfloat162_rn(
                            make_float2(d[mf][nf][2 * half], d[mf][nf][2 * half + 1]));
                }
            }
        }
    } else {
#pragma unroll
        for (int mf = 0; mf < 4; mf++) {
#pragma unroll
            for (int half = 0; half < 2; half++) {
                int gr = rbase + mf * 16 + half * 8;
#pragma unroll
                for (int nf = 0; nf < 8; nf++) {
                    int gc = col0 + cb2 + nf * 8;
                    *(float2*)(g_proj + (size_t)gr * DMODEL + gc) =
                        make_float2(d[mf][nf][2 * half], d[mf][nf][2 * half + 1]);
                }
            }
        }
    }
}

// fused QKV: blockIdx.z selects projection
__global__ void __launch_bounds__(128, 2)
gemm_qkv(const float* __restrict__ bq, const float* __restrict__ bk,
         const float* __restrict__ bv) {
    const int z = blockIdx.z;
    const __nv_bfloat16* A = (z == 0) ? g_xb  : (z == 1) ? g_kb  : g_vb;
    const __nv_bfloat16* W = (z == 0) ? g_Wqb : (z == 1) ? g_Wkb : g_Wvb;
    const float* bias      = (z == 0) ? bq    : (z == 1) ? bk    : bv;
    gemm_core(A, W, bias, z);
}

__global__ void __launch_bounds__(128, 2)
gemm_o(const float* __restrict__ bo) {
    gemm_core(g_ctxb, g_Wob, bo, 3);
}

// ---------------- Flash attention v3 (unchanged from R12) ---------------------
#define AQT 128
#define AKT 64
#define AALD 72
#define ATTN_SMEM ((AQT * AALD + 4 * AKT * AALD) * 2)   // 55296 B

__global__ void __launch_bounds__(256, 2)
attn_kernel() {
    extern __shared__ __align__(16) char smraw[];
    __nv_bfloat16* Qs = (__nv_bfloat16*)smraw;
    __nv_bfloat16* Ks0 = Qs + AQT * AALD;
    __nv_bfloat16* Vs0 = Ks0 + 2 * AKT * AALD;
    __nv_bfloat16* Ksb[2] = { Ks0, Ks0 + AKT * AALD };
    __nv_bfloat16* Vsb[2] = { Vs0, Vs0 + AKT * AALD };

    const int t = threadIdx.x;
    const int lane = t & 31;
    const int warp = t >> 5;
    const int q0 = blockIdx.x * AQT;
    const int bh = blockIdx.y;
    const __nv_bfloat16* Qg = g_Qb + (size_t)bh * SEQ * DK;
    const __nv_bfloat16* Kg = g_Kb + (size_t)bh * SEQ * DK;
    const __nv_bfloat16* Vg = g_Vb + (size_t)bh * SEQ * DK;

#pragma unroll
    for (int i = 0; i < 2; i++) {
        int idx = t + i * 256;
        int r = idx >> 3, v = idx & 7;
        cp_async16(Ksb[0] + r * AALD + v * 8, Kg + (size_t)r * DK + v * 8);
        cp_async16(Vsb[0] + r * AALD + v * 8, Vg + (size_t)r * DK + v * 8);
    }
    CP_COMMIT();

#pragma unroll
    for (int i = 0; i < 4; i++) {
        int idx = t + i * 256;
        int r = idx >> 3, v = idx & 7;
        *(uint4*)(Qs + r * AALD + v * 8) = *(const uint4*)(Qg + (size_t)(q0 + r) * DK + v * 8);
    }
    __syncthreads();

    uint32_t qa[4][4];
    {
        int row = warp * 16 + (lane & 15);
        int col8 = (lane >> 4) << 3;
#pragma unroll
        for (int ks = 0; ks < 4; ks++)
            ldmx4(qa[ks][0], qa[ks][1], qa[ks][2], qa[ks][3],
                  s2u(Qs + row * AALD + ks * 16 + col8));
    }

    float ofr[8][4];
#pragma unroll
    for (int f = 0; f < 8; f++)
#pragma unroll
        for (int e = 0; e < 4; e++) ofr[f][e] = 0.f;
    float mt0 = -1e30f, mt1 = -1e30f, l0 = 0.f, l1 = 0.f;

    const float CS = 0.125f * 1.4426950408889634f;

    const int NTILE = SEQ / AKT;
    for (int kt = 0; kt < NTILE; kt++) {
        const int buf = kt & 1;
        CP_WAIT0();
        __syncthreads();
        if (kt + 1 < NTILE) {
            const __nv_bfloat16* Kn = Kg + (size_t)(kt + 1) * AKT * DK;
            const __nv_bfloat16* Vn = Vg + (size_t)(kt + 1) * AKT * DK;
#pragma unroll
            for (int i = 0; i < 2; i++) {
                int idx = t + i * 256;
                int r = idx >> 3, v = idx & 7;
                cp_async16(Ksb[buf ^ 1] + r * AALD + v * 8, Kn + (size_t)r * DK + v * 8);
                cp_async16(Vsb[buf ^ 1] + r * AALD + v * 8, Vn + (size_t)r * DK + v * 8);
            }
            CP_COMMIT();
        }

        float sfr[8][4];
#pragma unroll
        for (int f = 0; f < 8; f++)
#pragma unroll
            for (int e = 0; e < 4; e++) sfr[f][e] = 0.f;

        {
            const __nv_bfloat16* Kt = Ksb[buf];
            int krow = (lane & 15);
            int kc8 = (lane >> 4) << 3;
#pragma unroll
            for (int ks = 0; ks < 4; ks++) {
#pragma unroll
                for (int fb = 0; fb < 4; fb++) {
                    uint32_t k0, k1, k2, k3;
                    ldmx4(k0, k1, k2, k3,
                          s2u(Kt + (fb * 16 + krow) * AALD + ks * 16 + kc8));
                    mma16816(sfr[2 * fb][0], sfr[2 * fb][1], sfr[2 * fb][2], sfr[2 * fb][3],
                             qa[ks][0], qa[ks][1], qa[ks][2], qa[ks][3], k0, k2);
                    mma16816(sfr[2 * fb + 1][0], sfr[2 * fb + 1][1], sfr[2 * fb + 1][2], sfr[2 * fb + 1][3],
                             qa[ks][0], qa[ks][1], qa[ks][2], qa[ks][3], k1, k3);
                }
            }
        }

        float mx0 = -1e30f, mx1 = -1e30f;
#pragma unroll
        for (int f = 0; f < 8; f++) {
            sfr[f][0] *= CS; sfr[f][1] *= CS; sfr[f][2] *= CS; sfr[f][3] *= CS;
            mx0 = fmaxf(mx0, fmaxf(sfr[f][0], sfr[f][1]));
            mx1 = fmaxf(mx1, fmaxf(sfr[f][2], sfr[f][3]));
        }
        mx0 = fmaxf(mx0, __shfl_xor_sync(0xffffffffu, mx0, 1));
        mx0 = fmaxf(mx0, __shfl_xor_sync(0xffffffffu, mx0, 2));
        mx1 = fmaxf(mx1, __shfl_xor_sync(0xffffffffu, mx1, 1));
        mx1 = fmaxf(mx1, __shfl_xor_sync(0xffffffffu, mx1, 2));
        float m0n = fmaxf(mt0, mx0), m1n = fmaxf(mt1, mx1);
        float al0 = fexp2(mt0 - m0n), al1 = fexp2(mt1 - m1n);
        mt0 = m0n; mt1 = m1n;

        float ps0 = 0.f, ps1 = 0.f;
#pragma unroll
        for (int f = 0; f < 8; f++) {
            sfr[f][0] = fexp2(sfr[f][0] - m0n);
            sfr[f][1] = fexp2(sfr[f][1] - m0n);
            sfr[f][2] = fexp2(sfr[f][2] - m1n);
            sfr[f][3] = fexp2(sfr[f][3] - m1n);
            ps0 += sfr[f][0] + sfr[f][1];
            ps1 += sfr[f][2] + sfr[f][3];
        }
        l0 = l0 * al0 + ps0;
        l1 = l1 * al1 + ps1;

#pragma unroll
        for (int f = 0; f < 8; f++) {
            ofr[f][0] *= al0; ofr[f][1] *= al0;
            ofr[f][2] *= al1; ofr[f][3] *= al1;
        }

        {
            const __nv_bfloat16* Vt = Vsb[buf];
            int vrow = (lane & 15);
            int vc8 = (lane >> 4) << 3;
#pragma unroll
            for (int ks = 0; ks < 4; ks++) {
                uint32_t a0 = packbf(sfr[2 * ks][0],     sfr[2 * ks][1]);
                uint32_t a1 = packbf(sfr[2 * ks][2],     sfr[2 * ks][3]);
                uint32_t a2 = packbf(sfr[2 * ks + 1][0], sfr[2 * ks + 1][1]);
                uint32_t a3 = packbf(sfr[2 * ks + 1][2], sfr[2 * ks + 1][3]);
#pragma unroll
                for (int fp = 0; fp < 4; fp++) {
                    uint32_t v0, v1, v2, v3;
                    ldmx4t(v0, v1, v2, v3,
                           s2u(Vt + (ks * 16 + vrow) * AALD + fp * 16 + vc8));
                    mma16816(ofr[2 * fp][0], ofr[2 * fp][1], ofr[2 * fp][2], ofr[2 * fp][3],
                             a0, a1, a2, a3, v0, v1);
                    mma16816(ofr[2 * fp + 1][0], ofr[2 * fp + 1][1], ofr[2 * fp + 1][2], ofr[2 * fp + 1][3],
                             a0, a1, a2, a3, v2, v3);
                }
            }
        }
    }

    l0 += __shfl_xor_sync(0xffffffffu, l0, 1);
    l0 += __shfl_xor_sync(0xffffffffu, l0, 2);
    l1 += __shfl_xor_sync(0xffffffffu, l1, 1);
    l1 += __shfl_xor_sync(0xffffffffu, l1, 2);
    float inv0 = 1.f / l0, inv1 = 1.f / l1;

    const int b = bh >> 4, h = bh & 15;
    int row0 = q0 + warp * 16 + (lane >> 2);
    int colb = h * DK + 2 * (lane & 3);
#pragma unroll
    for (int f = 0; f < 8; f++) {
        *(__nv_bfloat162*)(g_ctxb + (size_t)(b * SEQ + row0) * DMODEL + colb + f * 8) =
            __float22bfloat162_rn(make_float2(ofr[f][0] * inv0, ofr[f][1] * inv0));
        *(__nv_bfloat162*)(g_ctxb + (size_t)(b * SEQ + row0 + 8) * DMODEL + colb + f * 8) =
            __float22bfloat162_rn(make_float2(ofr[f][2] * inv1, ofr[f][3] * inv1));
    }
}

// ---------------- residual + LayerNorm ---------------------------------------
__global__ void __launch_bounds__(256)
ln_kernel(const float* __restrict__ residual, const float* __restrict__ gamma,
          const float* __restrict__ beta, float* __restrict__ out) {
    const int row = blockIdx.x;
    const int t = threadIdx.x;
    const size_t base = (size_t)row * DMODEL + t * 4;

    float4 r4 = *(const float4*)(residual + base);
    float4 p4 = *(const float4*)(g_proj + base);
    float x0 = r4.x + p4.x, x1 = r4.y + p4.y, x2 = r4.z + p4.z, x3 = r4.w + p4.w;

    float s = x0 + x1 + x2 + x3;
    float ss = x0 * x0 + x1 * x1 + x2 * x2 + x3 * x3;
#pragma unroll
    for (int off = 16; off > 0; off >>= 1) {
        s += __shfl_xor_sync(0xffffffffu, s, off);
        ss += __shfl_xor_sync(0xffffffffu, ss, off);
    }
    __shared__ float rs[8], rss[8], stat[2];
    int w = t >> 5, lane = t & 31;
    if (lane == 0) { rs[w] = s; rss[w] = ss; }
    __syncthreads();
    if (t == 0) {
        float S = 0.f, SS = 0.f;
#pragma unroll
        for (int i = 0; i < 8; i++) { S += rs[i]; SS += rss[i]; }
        float mean = S * (1.f / DMODEL);
        float var = SS * (1.f / DMODEL) - mean * mean;
        stat[0] = mean;
        stat[1] = rsqrtf(var + 1e-5f);
    }
    __syncthreads();
    float mean = stat[0], inv = stat[1];

    float4 g4 = *(const float4*)(gamma + t * 4);
    float4 b4 = *(const float4*)(beta + t * 4);
    float4 y;
    y.x = (x0 - mean) * inv * g4.x + b4.x;
    y.y = (x1 - mean) * inv * g4.y + b4.y;
    y.z = (x2 - mean) * inv * g4.z + b4.z;
    y.w = (x3 - mean) * inv * g4.w + b4.w;
    *(float4*)(out + base) = y;
}

// ---------------- launch ------------------------------------------------------
extern "C" void kernel_launch(void* const* d_in, const int* in_sizes, int n_in,
                              void* d_out, int out_size) {
    const float* query = (const float*)d_in[0];
    const float* key   = (const float*)d_in[1];
    const float* value = (const float*)d_in[2];
    const float* Wq    = (const float*)d_in[3];
    const float* bq    = (const float*)d_in[4];
    const float* Wk    = (const float*)d_in[5];
    const float* bk    = (const float*)d_in[6];
    const float* Wv    = (const float*)d_in[7];
    const float* bv    = (const float*)d_in[8];
    const float* Wo    = (const float*)d_in[9];
    const float* bo    = (const float*)d_in[10];
    const float* gamma = (const float*)d_in[11];
    const float* beta  = (const float*)d_in[12];
    float* out = (float*)d_out;

    static bool attr_done = false;
    if (!attr_done) {
        (void)cudaFuncSetAttribute(gemm_qkv,
                                   cudaFuncAttributeMaxDynamicSharedMemorySize, GEMM_SMEM);
        (void)cudaFuncSetAttribute(gemm_o,
                                   cudaFuncAttributeMaxDynamicSharedMemorySize, GEMM_SMEM);
        (void)cudaFuncSetAttribute(attn_kernel,
                                   cudaFuncAttributeMaxDynamicSharedMemorySize, ATTN_SMEM);
        attr_done = true;
    }

    const int n4_act = MTOT * DMODEL / 4;     // 2097152
    const int n4_w   = DMODEL * DMODEL / 4;   // 262144
    dim3 cgrid3(n4_act / 256, 1, 3);
    dim3 cgrid4(n4_w / 256, 1, 4);
    f2b3_kernel<<<cgrid3, 256>>>(query, key, value);
    f2b4_kernel<<<cgrid4, 256>>>(Wq, Wk, Wv, Wo);

    dim3 gq(DMODEL / GBN, MTOT / GBM, 3);   // (8, 64, 3)
    gemm_qkv<<<gq, 128, GEMM_SMEM>>>(bq, bk, bv);

    dim3 agrid(SEQ / AQT, BATCH * NHEADS);  // (16, 64)
    attn_kernel<<<agrid, 256, ATTN_SMEM>>>();

    dim3 go(DMODEL / GBN, MTOT / GBM);      // (8, 64)
    gemm_o<<<go, 128, GEMM_SMEM>>>(bo);

    ln_kernel<<<MTOT, 256>>>(query, gamma, beta, out);
}